// round 2
// baseline (speedup 1.0000x reference)
#include <cuda_runtime.h>
#include <math.h>

#define BB 4
#define SS 2048
#define DD 1024
#define DKK 128

// Scratch (device globals: allocation-free per harness rules)
__device__ float g_q[(size_t)BB * SS * DKK];          // 4 MB
__device__ float g_k[(size_t)BB * SS * DKK];          // 4 MB
__device__ float g_v[(size_t)BB * SS * DD];           // 32 MB
__device__ float g_p[(size_t)BB * SS * SS];           // 64 MB scores/probs

// ---------------------------------------------------------------------------
// Classic 128x128x8 fp32 SGEMM. A: [M,K] row-major. B: NN => [K,N] row-major,
// NT => [N,K] row-major (computes A @ B^T). C: [M,N] row-major.
// Batched via blockIdx.z with element strides.
// ---------------------------------------------------------------------------
template<bool TRANSB, bool BIAS>
__global__ __launch_bounds__(256, 2)
void sgemm128(const float* __restrict__ A, const float* __restrict__ Bm,
              const float* __restrict__ bias, float* __restrict__ C,
              int M, int N, int K,
              long long sA, long long sB, long long sC, float alpha)
{
    A  += (size_t)blockIdx.z * sA;
    Bm += (size_t)blockIdx.z * sB;
    C  += (size_t)blockIdx.z * sC;

    const int row0 = blockIdx.y * 128;
    const int col0 = blockIdx.x * 128;

    __shared__ float As[8][128];
    __shared__ float Bs[8][128];

    const int tid = threadIdx.x;
    const int ty  = tid >> 4;       // 0..15
    const int tx  = tid & 15;       // 0..15

    const int aRow = tid >> 1;          // 0..127
    const int aCol = (tid & 1) * 4;     // 0 or 4
    const int bRow = tid >> 5;          // 0..7  (k)
    const int bCol = (tid & 31) * 4;    // 0..124 (n)

    float acc[8][8];
    #pragma unroll
    for (int i = 0; i < 8; i++)
        #pragma unroll
        for (int j = 0; j < 8; j++) acc[i][j] = 0.0f;

    float ar[8], br[8];

    for (int k0 = 0; k0 < K; k0 += 8) {
        float4 av = *(const float4*)(A + (size_t)(row0 + aRow) * K + k0 + aCol);
        As[aCol + 0][aRow] = av.x;
        As[aCol + 1][aRow] = av.y;
        As[aCol + 2][aRow] = av.z;
        As[aCol + 3][aRow] = av.w;

        if (TRANSB) {
            float4 bv = *(const float4*)(Bm + (size_t)(col0 + aRow) * K + k0 + aCol);
            Bs[aCol + 0][aRow] = bv.x;
            Bs[aCol + 1][aRow] = bv.y;
            Bs[aCol + 2][aRow] = bv.z;
            Bs[aCol + 3][aRow] = bv.w;
        } else {
            float4 bv = *(const float4*)(Bm + (size_t)(k0 + bRow) * N + col0 + bCol);
            *(float4*)&Bs[bRow][bCol] = bv;
        }
        __syncthreads();

        #pragma unroll
        for (int kk = 0; kk < 8; kk++) {
            #pragma unroll
            for (int i = 0; i < 4; i++) {
                ar[i]     = As[kk][ty * 4 + i];
                ar[i + 4] = As[kk][64 + ty * 4 + i];
            }
            #pragma unroll
            for (int j = 0; j < 4; j++) {
                br[j]     = Bs[kk][tx * 4 + j];
                br[j + 4] = Bs[kk][64 + tx * 4 + j];
            }
            #pragma unroll
            for (int i = 0; i < 8; i++)
                #pragma unroll
                for (int j = 0; j < 8; j++)
                    acc[i][j] += ar[i] * br[j];
        }
        __syncthreads();
    }

    #pragma unroll
    for (int i = 0; i < 8; i++) {
        const int r = row0 + ((i < 4) ? (ty * 4 + i) : (64 + ty * 4 + i - 4));
        #pragma unroll
        for (int j = 0; j < 8; j++) {
            const int c = col0 + ((j < 4) ? (tx * 4 + j) : (64 + tx * 4 + j - 4));
            float val = alpha * acc[i][j];
            if (BIAS) val += bias[c];
            C[(size_t)r * N + c] = val;
        }
    }
}

// ---------------------------------------------------------------------------
// Masked causal softmax over rows of g_p, in place. Mask is int32 (0/1).
// Row (b, q): if query q padded -> uniform 1/S (reference all_neg edge case).
// Else softmax over valid k: k<=q && !pad[k], zeros elsewhere.
// ---------------------------------------------------------------------------
__global__ void masked_softmax(const int* __restrict__ mask)
{
    const int q = blockIdx.x;
    const int b = blockIdx.y;
    float* row = g_p + ((size_t)b * SS + q) * SS;
    const int tid = threadIdx.x;   // 256 threads, 8 elems each

    __shared__ float red[256];

    const bool padq = mask[b * SS + q] != 0;
    if (padq) {
        const float u = 1.0f / (float)SS;
        #pragma unroll
        for (int it = 0; it < 8; it++) row[tid + it * 256] = u;
        return;
    }

    float vals[8];
    float m = -INFINITY;
    #pragma unroll
    for (int it = 0; it < 8; it++) {
        const int k = tid + it * 256;
        const bool valid = (k <= q) && (mask[b * SS + k] == 0);
        const float s = valid ? row[k] : -INFINITY;
        vals[it] = s;
        m = fmaxf(m, s);
    }
    red[tid] = m;
    __syncthreads();
    for (int o = 128; o > 0; o >>= 1) {
        if (tid < o) red[tid] = fmaxf(red[tid], red[tid + o]);
        __syncthreads();
    }
    m = red[0];
    __syncthreads();

    float sum = 0.0f;
    #pragma unroll
    for (int it = 0; it < 8; it++) {
        const float e = (vals[it] == -INFINITY) ? 0.0f : __expf(vals[it] - m);
        vals[it] = e;
        sum += e;
    }
    red[tid] = sum;
    __syncthreads();
    for (int o = 128; o > 0; o >>= 1) {
        if (tid < o) red[tid] += red[tid + o];
        __syncthreads();
    }
    const float inv = 1.0f / red[0];

    #pragma unroll
    for (int it = 0; it < 8; it++) row[tid + it * 256] = vals[it] * inv;
}

// ---------------------------------------------------------------------------
extern "C" void kernel_launch(void* const* d_in, const int* in_sizes, int n_in,
                              void* d_out, int out_size)
{
    const float* x    = (const float*)d_in[0];
    const int*   mask = (const int*)d_in[1];      // bool promoted to int32 by harness
    const float* Wq   = (const float*)d_in[2];
    const float* bq   = (const float*)d_in[3];
    const float* Wk   = (const float*)d_in[4];
    const float* bk   = (const float*)d_in[5];
    const float* Wv   = (const float*)d_in[6];
    const float* bv   = (const float*)d_in[7];
    float* out = (float*)d_out;

    float *q, *k, *v, *p;
    cudaGetSymbolAddress((void**)&q, g_q);
    cudaGetSymbolAddress((void**)&k, g_k);
    cudaGetSymbolAddress((void**)&v, g_v);
    cudaGetSymbolAddress((void**)&p, g_p);

    const int M = BB * SS;                        // 8192
    const float scale = 1.0f / sqrtf((float)DKK); // 1/sqrt(128)

    // q = x @ Wq + bq   [8192,1024]x[1024,128]
    sgemm128<false, true><<<dim3(DKK / 128, M / 128, 1), 256>>>(
        x, Wq, bq, q, M, DKK, DD, 0, 0, 0, 1.0f);
    // k = x @ Wk + bk
    sgemm128<false, true><<<dim3(DKK / 128, M / 128, 1), 256>>>(
        x, Wk, bk, k, M, DKK, DD, 0, 0, 0, 1.0f);
    // v = x @ Wv + bv   [8192,1024]x[1024,1024]
    sgemm128<false, true><<<dim3(DD / 128, M / 128, 1), 256>>>(
        x, Wv, bv, v, M, DD, DD, 0, 0, 0, 1.0f);

    // scores = (q @ k^T) * scale, per batch   [2048,128]x[128,2048]
    sgemm128<true, false><<<dim3(SS / 128, SS / 128, BB), 256>>>(
        q, k, nullptr, p, SS, SS, DKK,
        (long long)SS * DKK, (long long)SS * DKK, (long long)SS * SS, scale);

    // masked softmax in place
    masked_softmax<<<dim3(SS, BB), 256>>>(mask);

    // out = P @ V, per batch   [2048,2048]x[2048,1024]
    sgemm128<false, false><<<dim3(DD / 128, SS / 128, BB), 256>>>(
        p, v, nullptr, out, SS, DD, SS,
        (long long)SS * SS, (long long)SS * DD, (long long)SS * DD, 1.0f);
}

// round 3
// speedup vs baseline: 1.1960x; 1.1960x over previous
#include <cuda_runtime.h>
#include <math.h>

#define BB 4
#define SS 2048
#define DD 1024
#define DKK 128

// Scratch (device globals: allocation-free per harness rules)
__device__ float g_q[(size_t)BB * SS * DKK];          // 4 MB
__device__ float g_k[(size_t)BB * SS * DKK];          // 4 MB
__device__ float g_v[(size_t)BB * SS * DD];           // 32 MB
__device__ float g_p[(size_t)BB * SS * SS];           // 64 MB scores/probs
__device__ float g_vmean[(size_t)BB * DD];            // 16 KB

// ---------------------------------------------------------------------------
// 128x128x16 fp32 SGEMM. A: [M,K] row-major. B: NN => [K,N] row-major,
// NT => [N,K] row-major (computes A @ B^T). C: [M,N] row-major.
// Batched via blockIdx.z. SKIP_UPPER: skip tiles above the diagonal (causal
// scores). CAUSAL_K: truncate K-loop to (blockIdx.y+1)*128 (P is strictly
// lower-triangular-supported).
// ---------------------------------------------------------------------------
template<bool TRANSB, bool BIAS, bool SKIP_UPPER, bool CAUSAL_K>
__global__ __launch_bounds__(256, 2)
void sgemm128(const float* __restrict__ A, const float* __restrict__ Bm,
              const float* __restrict__ bias, float* __restrict__ C,
              int M, int N, int K,
              long long sA, long long sB, long long sC, float alpha)
{
    if (SKIP_UPPER && blockIdx.x > blockIdx.y) return;

    A  += (size_t)blockIdx.z * sA;
    Bm += (size_t)blockIdx.z * sB;
    C  += (size_t)blockIdx.z * sC;

    const int row0 = blockIdx.y * 128;
    const int col0 = blockIdx.x * 128;

    int Keff = K;
    if (CAUSAL_K) {
        const int kl = (blockIdx.y + 1) * 128;
        Keff = kl < K ? kl : K;
    }

    __shared__ float As[16][128];
    __shared__ float Bs[16][128];

    const int tid = threadIdx.x;
    const int ty  = tid >> 4;       // 0..15
    const int tx  = tid & 15;       // 0..15

    const int aRow = tid >> 1;          // 0..127
    const int aCol = (tid & 1) * 8;     // 0 or 8
    const int bRow = tid >> 5;          // 0..7  (k)
    const int bCol = (tid & 31) * 4;    // 0..124 (n)

    float acc[8][8];
    #pragma unroll
    for (int i = 0; i < 8; i++)
        #pragma unroll
        for (int j = 0; j < 8; j++) acc[i][j] = 0.0f;

    float ar[8], br[8];

    for (int k0 = 0; k0 < Keff; k0 += 16) {
        {
            float4 a0 = *(const float4*)(A + (size_t)(row0 + aRow) * K + k0 + aCol);
            float4 a1 = *(const float4*)(A + (size_t)(row0 + aRow) * K + k0 + aCol + 4);
            As[aCol + 0][aRow] = a0.x; As[aCol + 1][aRow] = a0.y;
            As[aCol + 2][aRow] = a0.z; As[aCol + 3][aRow] = a0.w;
            As[aCol + 4][aRow] = a1.x; As[aCol + 5][aRow] = a1.y;
            As[aCol + 6][aRow] = a1.z; As[aCol + 7][aRow] = a1.w;
        }
        if (TRANSB) {
            float4 b0 = *(const float4*)(Bm + (size_t)(col0 + aRow) * K + k0 + aCol);
            float4 b1 = *(const float4*)(Bm + (size_t)(col0 + aRow) * K + k0 + aCol + 4);
            Bs[aCol + 0][aRow] = b0.x; Bs[aCol + 1][aRow] = b0.y;
            Bs[aCol + 2][aRow] = b0.z; Bs[aCol + 3][aRow] = b0.w;
            Bs[aCol + 4][aRow] = b1.x; Bs[aCol + 5][aRow] = b1.y;
            Bs[aCol + 6][aRow] = b1.z; Bs[aCol + 7][aRow] = b1.w;
        } else {
            float4 b0 = *(const float4*)(Bm + (size_t)(k0 + bRow) * N + col0 + bCol);
            float4 b1 = *(const float4*)(Bm + (size_t)(k0 + bRow + 8) * N + col0 + bCol);
            *(float4*)&Bs[bRow][bCol]     = b0;
            *(float4*)&Bs[bRow + 8][bCol] = b1;
        }
        __syncthreads();

        #pragma unroll
        for (int kk = 0; kk < 16; kk++) {
            #pragma unroll
            for (int i = 0; i < 4; i++) {
                ar[i]     = As[kk][ty * 4 + i];
                ar[i + 4] = As[kk][64 + ty * 4 + i];
            }
            #pragma unroll
            for (int j = 0; j < 4; j++) {
                br[j]     = Bs[kk][tx * 4 + j];
                br[j + 4] = Bs[kk][64 + tx * 4 + j];
            }
            #pragma unroll
            for (int i = 0; i < 8; i++)
                #pragma unroll
                for (int j = 0; j < 8; j++)
                    acc[i][j] += ar[i] * br[j];
        }
        __syncthreads();
    }

    #pragma unroll
    for (int i = 0; i < 8; i++) {
        const int r = row0 + ((i < 4) ? (ty * 4 + i) : (64 + ty * 4 + i - 4));
        #pragma unroll
        for (int j = 0; j < 8; j++) {
            const int c = col0 + ((j < 4) ? (tx * 4 + j) : (64 + tx * 4 + j - 4));
            float val = alpha * acc[i][j];
            if (BIAS) val += bias[c];
            C[(size_t)r * N + c] = val;
        }
    }
}

// ---------------------------------------------------------------------------
// Masked causal softmax over rows of g_p, in place. Mask is int32 (0/1).
// Padded query rows -> all zeros (their true output, mean of V, is scattered
// by a separate kernel). Non-padded: softmax over k<=q && !pad[k], zeros
// elsewhere. Result: P is strictly supported on k<=q.
// ---------------------------------------------------------------------------
__global__ void masked_softmax(const int* __restrict__ mask)
{
    const int q = blockIdx.x;
    const int b = blockIdx.y;
    float* row = g_p + ((size_t)b * SS + q) * SS;
    const int tid = threadIdx.x;   // 256 threads, 8 elems each

    __shared__ float red[256];

    const bool padq = mask[b * SS + q] != 0;
    if (padq) {
        #pragma unroll
        for (int it = 0; it < 8; it++) row[tid + it * 256] = 0.0f;
        return;
    }

    float vals[8];
    float m = -INFINITY;
    #pragma unroll
    for (int it = 0; it < 8; it++) {
        const int k = tid + it * 256;
        const bool valid = (k <= q) && (mask[b * SS + k] == 0);
        const float s = valid ? row[k] : -INFINITY;
        vals[it] = s;
        m = fmaxf(m, s);
    }
    red[tid] = m;
    __syncthreads();
    for (int o = 128; o > 0; o >>= 1) {
        if (tid < o) red[tid] = fmaxf(red[tid], red[tid + o]);
        __syncthreads();
    }
    m = red[0];
    __syncthreads();

    float sum = 0.0f;
    #pragma unroll
    for (int it = 0; it < 8; it++) {
        const float e = (vals[it] == -INFINITY) ? 0.0f : __expf(vals[it] - m);
        vals[it] = e;
        sum += e;
    }
    red[tid] = sum;
    __syncthreads();
    for (int o = 128; o > 0; o >>= 1) {
        if (tid < o) red[tid] += red[tid + o];
        __syncthreads();
    }
    const float inv = 1.0f / red[0];

    #pragma unroll
    for (int it = 0; it < 8; it++) row[tid + it * 256] = vals[it] * inv;
}

// ---------------------------------------------------------------------------
// Column mean of V per batch: g_vmean[b][d] = (1/S) * sum_k v[b][k][d]
// ---------------------------------------------------------------------------
__global__ void v_colmean()
{
    const int d = blockIdx.x * 256 + threadIdx.x;  // 0..1023
    const int b = blockIdx.y;
    const float* vb = g_v + (size_t)b * SS * DD + d;
    float s = 0.0f;
    for (int k = 0; k < SS; k++) s += vb[(size_t)k * DD];
    g_vmean[b * DD + d] = s * (1.0f / (float)SS);
}

// ---------------------------------------------------------------------------
// Overwrite padded-query output rows with the V column mean (uniform attn).
// ---------------------------------------------------------------------------
__global__ void scatter_padded(const int* __restrict__ mask, float* __restrict__ out)
{
    const int q = blockIdx.x;
    const int b = blockIdx.y;
    if (mask[b * SS + q] == 0) return;
    const int tid = threadIdx.x;   // 256 threads, 4 elems each
    float* o = out + ((size_t)b * SS + q) * DD;
    const float* vm = g_vmean + b * DD;
    #pragma unroll
    for (int it = 0; it < 4; it++) o[tid + it * 256] = vm[tid + it * 256];
}

// ---------------------------------------------------------------------------
extern "C" void kernel_launch(void* const* d_in, const int* in_sizes, int n_in,
                              void* d_out, int out_size)
{
    const float* x    = (const float*)d_in[0];
    const int*   mask = (const int*)d_in[1];      // bool promoted to int32
    const float* Wq   = (const float*)d_in[2];
    const float* bq   = (const float*)d_in[3];
    const float* Wk   = (const float*)d_in[4];
    const float* bk   = (const float*)d_in[5];
    const float* Wv   = (const float*)d_in[6];
    const float* bv   = (const float*)d_in[7];
    float* out = (float*)d_out;

    float *q, *k, *v, *p;
    cudaGetSymbolAddress((void**)&q, g_q);
    cudaGetSymbolAddress((void**)&k, g_k);
    cudaGetSymbolAddress((void**)&v, g_v);
    cudaGetSymbolAddress((void**)&p, g_p);

    const int M = BB * SS;                        // 8192
    const float scale = 1.0f / sqrtf((float)DKK); // 1/sqrt(128)

    // q = x @ Wq + bq   [8192,1024]x[1024,128]
    sgemm128<false, true, false, false><<<dim3(DKK / 128, M / 128, 1), 256>>>(
        x, Wq, bq, q, M, DKK, DD, 0, 0, 0, 1.0f);
    // k = x @ Wk + bk
    sgemm128<false, true, false, false><<<dim3(DKK / 128, M / 128, 1), 256>>>(
        x, Wk, bk, k, M, DKK, DD, 0, 0, 0, 1.0f);
    // v = x @ Wv + bv   [8192,1024]x[1024,1024]
    sgemm128<false, true, false, false><<<dim3(DD / 128, M / 128, 1), 256>>>(
        x, Wv, bv, v, M, DD, DD, 0, 0, 0, 1.0f);

    // scores = (q @ k^T) * scale, per batch, lower-triangle tiles only
    sgemm128<true, false, true, false><<<dim3(SS / 128, SS / 128, BB), 256>>>(
        q, k, nullptr, p, SS, SS, DKK,
        (long long)SS * DKK, (long long)SS * DKK, (long long)SS * SS, scale);

    // masked softmax in place (padded rows -> zeros)
    masked_softmax<<<dim3(SS, BB), 256>>>(mask);

    // V column means (for padded-query rows)
    v_colmean<<<dim3(DD / 256, BB), 256>>>();

    // out = P @ V, per batch, K truncated to causal extent
    sgemm128<false, false, false, true><<<dim3(DD / 128, SS / 128, BB), 256>>>(
        p, v, nullptr, out, SS, DD, SS,
        (long long)SS * SS, (long long)SS * DD, (long long)SS * DD, 1.0f);

    // overwrite padded rows with uniform-attention result
    scatter_padded<<<dim3(SS, BB), 256>>>(mask, out);
}

// round 5
// speedup vs baseline: 2.6413x; 2.2084x over previous
#include <cuda_runtime.h>
#include <cuda_bf16.h>
#include <math.h>
#include <stdint.h>

#define BB 4
#define SS 2048
#define DD 1024
#define DKK 128
#define MTOT (BB * SS)   // 8192

// ---------------------------------------------------------------------------
// Device scratch (allocation-free per harness rules)
// ---------------------------------------------------------------------------
__device__ __nv_bfloat16 g_xh[(size_t)MTOT * DD];
__device__ __nv_bfloat16 g_xl[(size_t)MTOT * DD];
__device__ __nv_bfloat16 g_wqt_h[DKK * DD], g_wqt_l[DKK * DD];
__device__ __nv_bfloat16 g_wkt_h[DKK * DD], g_wkt_l[DKK * DD];
__device__ __nv_bfloat16 g_wvt_h[DD * DD],  g_wvt_l[DD * DD];
__device__ float g_qf[(size_t)MTOT * DKK];
__device__ float g_kf[(size_t)MTOT * DKK];
__device__ __nv_bfloat16 g_qh[(size_t)MTOT * DKK], g_ql[(size_t)MTOT * DKK];
__device__ __nv_bfloat16 g_kh[(size_t)MTOT * DKK], g_kl[(size_t)MTOT * DKK];
__device__ float g_v[(size_t)MTOT * DD];
__device__ __nv_bfloat16 g_vth[(size_t)BB * DD * SS], g_vtl[(size_t)BB * DD * SS];
__device__ float g_s[(size_t)BB * SS * SS];
__device__ __nv_bfloat16 g_ph[(size_t)BB * SS * SS], g_pl[(size_t)BB * SS * SS];
__device__ float g_vmean[BB * DD];

// ---------------------------------------------------------------------------
// mma.sync + cp.async helpers (plain compute_103-safe PTX, sm_80+)
// ---------------------------------------------------------------------------
__device__ __forceinline__ uint32_t smem_u32(const void* p) {
    uint32_t a;
    asm("{ .reg .u64 t; cvta.to.shared.u64 t, %1; cvt.u32.u64 %0, t; }"
        : "=r"(a) : "l"(p));
    return a;
}
__device__ __forceinline__ void cp_async16(uint32_t dst, const void* src) {
    asm volatile("cp.async.cg.shared.global [%0], [%1], 16;"
                 :: "r"(dst), "l"(src) : "memory");
}
__device__ __forceinline__ void cp_commit() {
    asm volatile("cp.async.commit_group;" ::: "memory");
}
template<int N>
__device__ __forceinline__ void cp_wait() {
    asm volatile("cp.async.wait_group %0;" :: "n"(N) : "memory");
}
__device__ __forceinline__ void mma16816(float* c, const uint32_t* a, const uint32_t* b) {
    asm volatile(
        "mma.sync.aligned.m16n8k16.row.col.f32.bf16.bf16.f32 "
        "{%0,%1,%2,%3}, {%4,%5,%6,%7}, {%8,%9}, {%0,%1,%2,%3};"
        : "+f"(c[0]), "+f"(c[1]), "+f"(c[2]), "+f"(c[3])
        : "r"(a[0]), "r"(a[1]), "r"(a[2]), "r"(a[3]), "r"(b[0]), "r"(b[1]));
}

// ---------------------------------------------------------------------------
// bf16x3 GEMM on HMMA (mma.sync).  C[M,N] fp32 = alpha*(A @ B^T) (+ bias).
// A given as bf16 (hi,lo) [M,K]; B as bf16 (hi,lo) [N,K]; both K-major.
// CTA tile 128x128, warp tile 64x32, K-chunk 32, 3-stage cp.async pipeline.
// SMEM row stride 80 B (16B-aligned, conflict-free fragment loads).
// ---------------------------------------------------------------------------
#define ROWB 80
#define SM_TILE (128 * ROWB)            // 10240
#define STAGE_BYTES (4 * SM_TILE)       // 40960: Ah, Al, Bh, Bl
#define NSTAGE 3
#define SMEM_BYTES (NSTAGE * STAGE_BYTES)  // 122880

template<bool SKIP_UPPER, bool CAUSAL_K, bool BIAS>
__global__ void __launch_bounds__(256, 1)
gemm_bf16x3(const __nv_bfloat16* __restrict__ Ah, const __nv_bfloat16* __restrict__ Al,
            const __nv_bfloat16* __restrict__ Bh, const __nv_bfloat16* __restrict__ Bl,
            const float* __restrict__ bias, float* __restrict__ C,
            int M, int N, int K,
            long long sA, long long sB, long long sC, float alpha)
{
    if (SKIP_UPPER && blockIdx.x > blockIdx.y) return;
    extern __shared__ char smem[];

    const int tid = threadIdx.x;
    const int wid = tid >> 5, lane = tid & 31;
    const int wr = wid >> 2;        // 0..1  warp row (64 rows)
    const int wc = wid & 3;         // 0..3  warp col (32 cols)
    const int r4 = lane >> 2;       // 0..7
    const int c4 = lane & 3;        // 0..3

    Ah += (size_t)blockIdx.z * sA;  Al += (size_t)blockIdx.z * sA;
    Bh += (size_t)blockIdx.z * sB;  Bl += (size_t)blockIdx.z * sB;
    C  += (size_t)blockIdx.z * sC;

    const int row0 = blockIdx.y * 128;
    const int col0 = blockIdx.x * 128;

    int Keff = K;
    if (CAUSAL_K) { const int kl = (blockIdx.y + 1) * 128; Keff = kl < K ? kl : K; }
    const int nchunk = Keff >> 5;   // K-chunk = 32

    const uint32_t sb = smem_u32(smem);

    // loader: per tile, 2 cp.async of 16B per thread (128 rows x 64 B)
    auto ldstage = [&](int c, int s) {
        const long long kofs = (long long)c * 32;
        const uint32_t st = sb + s * STAGE_BYTES;
        const __nv_bfloat16* G[4] = { Ah, Al, Bh, Bl };
        #pragma unroll
        for (int t = 0; t < 4; t++) {
            const int r0 = (t < 2) ? row0 : col0;
            #pragma unroll
            for (int o = 0; o < 2; o++) {
                const int lin = tid + o * 256;
                const int row = lin >> 2;
                const int cb  = (lin & 3) * 16;
                const char* src = (const char*)G[t] + ((size_t)(r0 + row) * K + kofs) * 2 + cb;
                cp_async16(st + t * SM_TILE + row * ROWB + cb, src);
            }
        }
        cp_commit();
    };

    float acc[4][4][4];
    #pragma unroll
    for (int i = 0; i < 4; i++)
        #pragma unroll
        for (int j = 0; j < 4; j++)
            #pragma unroll
            for (int r = 0; r < 4; r++) acc[i][j][r] = 0.0f;

    ldstage(0, 0);
    if (nchunk > 1) ldstage(1, 1); else cp_commit();

    for (int c = 0; c < nchunk; c++) {
        if (c + 2 < nchunk) ldstage(c + 2, (c + 2) % NSTAGE);
        else cp_commit();                 // keep group bookkeeping uniform
        cp_wait<2>();
        __syncthreads();                  // stage c visible to all warps

        const char* stp = smem + (c % NSTAGE) * STAGE_BYTES;
        #pragma unroll
        for (int ks = 0; ks < 2; ks++) {
            const int cb = ks * 32 + c4 * 4;     // byte offset in 64B row
            // B fragments for the 4 n-tiles
            uint32_t bh[4][2], bl[4][2];
            #pragma unroll
            for (int nt = 0; nt < 4; nt++) {
                const int off = (wc * 32 + nt * 8 + r4) * ROWB + cb;
                bh[nt][0] = *(const uint32_t*)(stp + 2 * SM_TILE + off);
                bh[nt][1] = *(const uint32_t*)(stp + 2 * SM_TILE + off + 16);
                bl[nt][0] = *(const uint32_t*)(stp + 3 * SM_TILE + off);
                bl[nt][1] = *(const uint32_t*)(stp + 3 * SM_TILE + off + 16);
            }
            #pragma unroll
            for (int mt = 0; mt < 4; mt++) {
                const int off0 = (wr * 64 + mt * 16 + r4) * ROWB + cb;
                const int off1 = off0 + 8 * ROWB;
                uint32_t ah[4], al[4];
                ah[0] = *(const uint32_t*)(stp + off0);
                ah[1] = *(const uint32_t*)(stp + off1);
                ah[2] = *(const uint32_t*)(stp + off0 + 16);
                ah[3] = *(const uint32_t*)(stp + off1 + 16);
                al[0] = *(const uint32_t*)(stp + SM_TILE + off0);
                al[1] = *(const uint32_t*)(stp + SM_TILE + off1);
                al[2] = *(const uint32_t*)(stp + SM_TILE + off0 + 16);
                al[3] = *(const uint32_t*)(stp + SM_TILE + off1 + 16);
                #pragma unroll
                for (int nt = 0; nt < 4; nt++) {
                    mma16816(acc[mt][nt], ah, bh[nt]);
                    mma16816(acc[mt][nt], ah, bl[nt]);
                    mma16816(acc[mt][nt], al, bh[nt]);
                }
            }
        }
        __syncthreads();                  // all warps done before buffer reuse
    }

    // epilogue
    #pragma unroll
    for (int mt = 0; mt < 4; mt++) {
        const int r = row0 + wr * 64 + mt * 16 + r4;
        #pragma unroll
        for (int nt = 0; nt < 4; nt++) {
            const int cidx = col0 + wc * 32 + nt * 8 + c4 * 2;
            float b0 = 0.f, b1 = 0.f;
            if (BIAS) { b0 = __ldg(bias + cidx); b1 = __ldg(bias + cidx + 1); }
            float2 v0 = { alpha * acc[mt][nt][0] + b0, alpha * acc[mt][nt][1] + b1 };
            float2 v1 = { alpha * acc[mt][nt][2] + b0, alpha * acc[mt][nt][3] + b1 };
            *(float2*)(C + (size_t)r * N + cidx)       = v0;
            *(float2*)(C + (size_t)(r + 8) * N + cidx) = v1;
        }
    }
}

// ---------------------------------------------------------------------------
// fp32 -> bf16 (hi, lo) elementwise split, float4-vectorized
// ---------------------------------------------------------------------------
__device__ __forceinline__ void split1(float x, __nv_bfloat16& h, __nv_bfloat16& l) {
    h = __float2bfloat16(x);
    l = __float2bfloat16(x - __bfloat162float(h));
}
__global__ void split_fp32(const float* __restrict__ src,
                           __nv_bfloat16* __restrict__ hi, __nv_bfloat16* __restrict__ lo,
                           long long n4)
{
    const long long i = (long long)blockIdx.x * blockDim.x + threadIdx.x;
    if (i >= n4) return;
    float4 v = ((const float4*)src)[i];
    __nv_bfloat16 h0, h1, h2, h3, l0, l1, l2, l3;
    split1(v.x, h0, l0); split1(v.y, h1, l1); split1(v.z, h2, l2); split1(v.w, h3, l3);
    __nv_bfloat162* H = (__nv_bfloat162*)hi;
    __nv_bfloat162* L = (__nv_bfloat162*)lo;
    H[2 * i]     = __nv_bfloat162(h0, h1);
    H[2 * i + 1] = __nv_bfloat162(h2, h3);
    L[2 * i]     = __nv_bfloat162(l0, l1);
    L[2 * i + 1] = __nv_bfloat162(l2, l3);
}

// ---------------------------------------------------------------------------
// fp32 [R,C] -> transposed bf16 hi/lo [C,R], batched; tiled 32x32
// ---------------------------------------------------------------------------
__global__ void transpose_split(const float* __restrict__ in,
                                __nv_bfloat16* __restrict__ oh, __nv_bfloat16* __restrict__ ol,
                                int R, int C, long long sIn, long long sOut)
{
    __shared__ float t[32][33];
    in += (size_t)blockIdx.z * sIn;
    oh += (size_t)blockIdx.z * sOut;
    ol += (size_t)blockIdx.z * sOut;
    const int c0 = blockIdx.x * 32, r0 = blockIdx.y * 32;
    const int tx = threadIdx.x & 31, ty = threadIdx.x >> 5;   // 256 thr: ty 0..7
    #pragma unroll
    for (int k = 0; k < 32; k += 8)
        t[ty + k][tx] = in[(size_t)(r0 + ty + k) * C + c0 + tx];
    __syncthreads();
    #pragma unroll
    for (int k = 0; k < 32; k += 8) {
        __nv_bfloat16 h, l;
        split1(t[tx][ty + k], h, l);
        oh[(size_t)(c0 + ty + k) * R + r0 + tx] = h;
        ol[(size_t)(c0 + ty + k) * R + r0 + tx] = l;
    }
}

// ---------------------------------------------------------------------------
// Masked causal softmax: reads fp32 scores, writes bf16 hi/lo P.
// Padded query rows -> zeros (handled later by scatter_padded).
// ---------------------------------------------------------------------------
__global__ void masked_softmax(const int* __restrict__ mask)
{
    const int q = blockIdx.x;
    const int b = blockIdx.y;
    const size_t off = ((size_t)b * SS + q) * SS;
    const float* row = g_s + off;
    __nv_bfloat16* ph = g_ph + off;
    __nv_bfloat16* pl = g_pl + off;
    const int tid = threadIdx.x;   // 256 threads, 8 elems each

    __shared__ float red[256];

    if (mask[b * SS + q] != 0) {
        #pragma unroll
        for (int it = 0; it < 8; it++) {
            ph[tid + it * 256] = __float2bfloat16(0.0f);
            pl[tid + it * 256] = __float2bfloat16(0.0f);
        }
        return;
    }

    float vals[8];
    float m = -INFINITY;
    #pragma unroll
    for (int it = 0; it < 8; it++) {
        const int k = tid + it * 256;
        const bool valid = (k <= q) && (mask[b * SS + k] == 0);
        const float s = valid ? row[k] : -INFINITY;
        vals[it] = s;
        m = fmaxf(m, s);
    }
    red[tid] = m;
    __syncthreads();
    for (int o = 128; o > 0; o >>= 1) {
        if (tid < o) red[tid] = fmaxf(red[tid], red[tid + o]);
        __syncthreads();
    }
    m = red[0];
    __syncthreads();

    float sum = 0.0f;
    #pragma unroll
    for (int it = 0; it < 8; it++) {
        const float e = (vals[it] == -INFINITY) ? 0.0f : __expf(vals[it] - m);
        vals[it] = e;
        sum += e;
    }
    red[tid] = sum;
    __syncthreads();
    for (int o = 128; o > 0; o >>= 1) {
        if (tid < o) red[tid] += red[tid + o];
        __syncthreads();
    }
    const float inv = 1.0f / red[0];

    #pragma unroll
    for (int it = 0; it < 8; it++) {
        __nv_bfloat16 h, l;
        split1(vals[it] * inv, h, l);
        ph[tid + it * 256] = h;
        pl[tid + it * 256] = l;
    }
}

// ---------------------------------------------------------------------------
__global__ void v_colmean()
{
    const int d = blockIdx.x * 256 + threadIdx.x;
    const int b = blockIdx.y;
    const float* vb = g_v + (size_t)b * SS * DD + d;
    float s = 0.0f;
    for (int k = 0; k < SS; k++) s += vb[(size_t)k * DD];
    g_vmean[b * DD + d] = s * (1.0f / (float)SS);
}

__global__ void scatter_padded(const int* __restrict__ mask, float* __restrict__ out)
{
    const int q = blockIdx.x;
    const int b = blockIdx.y;
    if (mask[b * SS + q] == 0) return;
    const int tid = threadIdx.x;
    float* o = out + ((size_t)b * SS + q) * DD;
    const float* vm = g_vmean + b * DD;
    #pragma unroll
    for (int it = 0; it < 4; it++) o[tid + it * 256] = vm[tid + it * 256];
}

// ---------------------------------------------------------------------------
extern "C" void kernel_launch(void* const* d_in, const int* in_sizes, int n_in,
                              void* d_out, int out_size)
{
    const float* x    = (const float*)d_in[0];
    const int*   mask = (const int*)d_in[1];
    const float* Wq   = (const float*)d_in[2];
    const float* bq   = (const float*)d_in[3];
    const float* Wk   = (const float*)d_in[4];
    const float* bk   = (const float*)d_in[5];
    const float* Wv   = (const float*)d_in[6];
    const float* bv   = (const float*)d_in[7];
    float* out = (float*)d_out;

    cudaFuncSetAttribute(gemm_bf16x3<false, false, true>,
                         cudaFuncAttributeMaxDynamicSharedMemorySize, SMEM_BYTES);
    cudaFuncSetAttribute(gemm_bf16x3<true, false, false>,
                         cudaFuncAttributeMaxDynamicSharedMemorySize, SMEM_BYTES);
    cudaFuncSetAttribute(gemm_bf16x3<false, true, false>,
                         cudaFuncAttributeMaxDynamicSharedMemorySize, SMEM_BYTES);

    __nv_bfloat16 *xh, *xl, *wqth, *wqtl, *wkth, *wktl, *wvth, *wvtl;
    __nv_bfloat16 *qh, *ql, *kh, *kl, *vth, *vtl, *ph, *pl;
    float *qf, *kf, *v, *s;
    cudaGetSymbolAddress((void**)&xh, g_xh);     cudaGetSymbolAddress((void**)&xl, g_xl);
    cudaGetSymbolAddress((void**)&wqth, g_wqt_h); cudaGetSymbolAddress((void**)&wqtl, g_wqt_l);
    cudaGetSymbolAddress((void**)&wkth, g_wkt_h); cudaGetSymbolAddress((void**)&wktl, g_wkt_l);
    cudaGetSymbolAddress((void**)&wvth, g_wvt_h); cudaGetSymbolAddress((void**)&wvtl, g_wvt_l);
    cudaGetSymbolAddress((void**)&qf, g_qf);     cudaGetSymbolAddress((void**)&kf, g_kf);
    cudaGetSymbolAddress((void**)&qh, g_qh);     cudaGetSymbolAddress((void**)&ql, g_ql);
    cudaGetSymbolAddress((void**)&kh, g_kh);     cudaGetSymbolAddress((void**)&kl, g_kl);
    cudaGetSymbolAddress((void**)&v, g_v);
    cudaGetSymbolAddress((void**)&vth, g_vth);   cudaGetSymbolAddress((void**)&vtl, g_vtl);
    cudaGetSymbolAddress((void**)&s, g_s);
    cudaGetSymbolAddress((void**)&ph, g_ph);     cudaGetSymbolAddress((void**)&pl, g_pl);

    const float scale = 1.0f / sqrtf((float)DKK);

    // 1. split x into bf16 hi/lo
    {
        long long n4 = (long long)MTOT * DD / 4;
        split_fp32<<<(unsigned)((n4 + 255) / 256), 256>>>(x, xh, xl, n4);
    }
    // 2. transpose + split weights:  W[K,N] -> WT[N,K]
    transpose_split<<<dim3(DKK / 32, DD / 32, 1), 256>>>(Wq, wqth, wqtl, DD, DKK, 0, 0);
    transpose_split<<<dim3(DKK / 32, DD / 32, 1), 256>>>(Wk, wkth, wktl, DD, DKK, 0, 0);
    transpose_split<<<dim3(DD / 32, DD / 32, 1), 256>>>(Wv, wvth, wvtl, DD, DD, 0, 0);

    // 3. projections (HMMA): q, k [8192,128]; v [8192,1024]
    gemm_bf16x3<false, false, true><<<dim3(1, MTOT / 128, 1), 256, SMEM_BYTES>>>(
        xh, xl, wqth, wqtl, bq, qf, MTOT, DKK, DD, 0, 0, 0, 1.0f);
    gemm_bf16x3<false, false, true><<<dim3(1, MTOT / 128, 1), 256, SMEM_BYTES>>>(
        xh, xl, wkth, wktl, bk, kf, MTOT, DKK, DD, 0, 0, 0, 1.0f);
    gemm_bf16x3<false, false, true><<<dim3(DD / 128, MTOT / 128, 1), 256, SMEM_BYTES>>>(
        xh, xl, wvth, wvtl, bv, v, MTOT, DD, DD, 0, 0, 0, 1.0f);

    // 4. split q, k; transpose+split v per batch; V column means
    {
        long long n4 = (long long)MTOT * DKK / 4;
        split_fp32<<<(unsigned)((n4 + 255) / 256), 256>>>(qf, qh, ql, n4);
        split_fp32<<<(unsigned)((n4 + 255) / 256), 256>>>(kf, kh, kl, n4);
    }
    transpose_split<<<dim3(DD / 32, SS / 32, BB), 256>>>(
        v, vth, vtl, SS, DD, (long long)SS * DD, (long long)SS * DD);
    v_colmean<<<dim3(DD / 256, BB), 256>>>();

    // 5. scores = (q @ k^T) * scale, per batch, lower-triangle tiles only
    gemm_bf16x3<true, false, false><<<dim3(SS / 128, SS / 128, BB), 256, SMEM_BYTES>>>(
        qh, ql, kh, kl, nullptr, s, SS, SS, DKK,
        (long long)SS * DKK, (long long)SS * DKK, (long long)SS * SS, scale);

    // 6. masked softmax -> P (bf16 hi/lo)
    masked_softmax<<<dim3(SS, BB), 256>>>(mask);

    // 7. out = P @ V (V given transposed as [D, S]), K truncated causally
    gemm_bf16x3<false, true, false><<<dim3(DD / 128, SS / 128, BB), 256, SMEM_BYTES>>>(
        ph, pl, vth, vtl, nullptr, out, SS, DD, SS,
        (long long)SS * SS, (long long)DD * SS, (long long)SS * DD, 1.0f);

    // 8. padded rows <- uniform attention (V column mean)
    scatter_padded<<<dim3(SS, BB), 256>>>(mask, out);
}

// round 6
// speedup vs baseline: 2.6740x; 1.0124x over previous
#include <cuda_runtime.h>
#include <cuda_bf16.h>
#include <math.h>
#include <stdint.h>

#define BB 4
#define SS 2048
#define DD 1024
#define DKK 128
#define MTOT (BB * SS)   // 8192

// ---------------------------------------------------------------------------
// Device scratch (allocation-free per harness rules)
// ---------------------------------------------------------------------------
__device__ __nv_bfloat16 g_xh[(size_t)MTOT * DD];
__device__ __nv_bfloat16 g_xl[(size_t)MTOT * DD];
__device__ __nv_bfloat16 g_wqt_h[DKK * DD], g_wqt_l[DKK * DD];
__device__ __nv_bfloat16 g_wkt_h[DKK * DD], g_wkt_l[DKK * DD];
__device__ __nv_bfloat16 g_wvt_h[DD * DD],  g_wvt_l[DD * DD];
__device__ __nv_bfloat16 g_qh[(size_t)MTOT * DKK], g_ql[(size_t)MTOT * DKK];
__device__ __nv_bfloat16 g_kh[(size_t)MTOT * DKK], g_kl[(size_t)MTOT * DKK];
__device__ float g_v[(size_t)MTOT * DD];
__device__ __nv_bfloat16 g_vth[(size_t)BB * DD * SS], g_vtl[(size_t)BB * DD * SS];
__device__ float g_s[(size_t)BB * SS * SS];
__device__ __nv_bfloat16 g_ph[(size_t)BB * SS * SS], g_pl[(size_t)BB * SS * SS];
__device__ float g_vmean[BB * DD];

// ---------------------------------------------------------------------------
// mma.sync + cp.async + ldmatrix helpers (plain compute_103-safe PTX)
// ---------------------------------------------------------------------------
__device__ __forceinline__ uint32_t smem_u32(const void* p) {
    uint32_t a;
    asm("{ .reg .u64 t; cvta.to.shared.u64 t, %1; cvt.u32.u64 %0, t; }"
        : "=r"(a) : "l"(p));
    return a;
}
__device__ __forceinline__ void cp_async16(uint32_t dst, const void* src) {
    asm volatile("cp.async.cg.shared.global [%0], [%1], 16;"
                 :: "r"(dst), "l"(src) : "memory");
}
__device__ __forceinline__ void cp_commit() {
    asm volatile("cp.async.commit_group;" ::: "memory");
}
template<int N>
__device__ __forceinline__ void cp_wait() {
    asm volatile("cp.async.wait_group %0;" :: "n"(N) : "memory");
}
__device__ __forceinline__ void mma16816(float* c, const uint32_t* a, const uint32_t* b) {
    asm volatile(
        "mma.sync.aligned.m16n8k16.row.col.f32.bf16.bf16.f32 "
        "{%0,%1,%2,%3}, {%4,%5,%6,%7}, {%8,%9}, {%0,%1,%2,%3};"
        : "+f"(c[0]), "+f"(c[1]), "+f"(c[2]), "+f"(c[3])
        : "r"(a[0]), "r"(a[1]), "r"(a[2]), "r"(a[3]), "r"(b[0]), "r"(b[1]));
}
__device__ __forceinline__ void ldsm_x4(uint32_t* r, uint32_t addr) {
    asm volatile("ldmatrix.sync.aligned.m8n8.x4.shared.b16 {%0,%1,%2,%3}, [%4];"
                 : "=r"(r[0]), "=r"(r[1]), "=r"(r[2]), "=r"(r[3]) : "r"(addr));
}
__device__ __forceinline__ void ldsm_x2(uint32_t* r, uint32_t addr) {
    asm volatile("ldmatrix.sync.aligned.m8n8.x2.shared.b16 {%0,%1}, [%2];"
                 : "=r"(r[0]), "=r"(r[1]) : "r"(addr));
}

__device__ __forceinline__ void split1(float x, __nv_bfloat16& h, __nv_bfloat16& l) {
    h = __float2bfloat16(x);
    l = __float2bfloat16(x - __bfloat162float(h));
}

// ---------------------------------------------------------------------------
// bf16x3 GEMM on HMMA (mma.sync + ldmatrix).
// C[M,N] = alpha*(A @ B^T) (+ bias);  A bf16 (hi,lo) [M,K], B bf16 (hi,lo)
// [N,K], both K-major.  CTA tile 128x128, warp tile 64x32, K-chunk 32,
// 3-stage cp.async pipeline.  SMEM row stride 80 B (conflict-free).
// OUT_SPLIT: write bf16 (hi,lo) instead of fp32 C.
// ---------------------------------------------------------------------------
#define ROWB 80
#define SM_TILE (128 * ROWB)            // 10240
#define STAGE_BYTES (4 * SM_TILE)       // 40960: Ah, Al, Bh, Bl
#define NSTAGE 3
#define SMEM_BYTES (NSTAGE * STAGE_BYTES)  // 122880

template<bool SKIP_UPPER, bool CAUSAL_K, bool BIAS, bool OUT_SPLIT>
__global__ void __launch_bounds__(256, 1)
gemm_bf16x3(const __nv_bfloat16* __restrict__ Ah, const __nv_bfloat16* __restrict__ Al,
            const __nv_bfloat16* __restrict__ Bh, const __nv_bfloat16* __restrict__ Bl,
            const float* __restrict__ bias, float* __restrict__ C,
            __nv_bfloat16* __restrict__ Ch, __nv_bfloat16* __restrict__ Cl,
            int M, int N, int K,
            long long sA, long long sB, long long sC, float alpha)
{
    if (SKIP_UPPER && blockIdx.x > blockIdx.y) return;
    extern __shared__ char smem[];

    const int tid = threadIdx.x;
    const int wid = tid >> 5, lane = tid & 31;
    const int wr = wid >> 2;        // 0..1  warp row (64 rows)
    const int wc = wid & 3;         // 0..3  warp col (32 cols)
    const int r4 = lane >> 2;       // 0..7
    const int c4 = lane & 3;        // 0..3

    Ah += (size_t)blockIdx.z * sA;  Al += (size_t)blockIdx.z * sA;
    Bh += (size_t)blockIdx.z * sB;  Bl += (size_t)blockIdx.z * sB;

    const int row0 = blockIdx.y * 128;
    const int col0 = blockIdx.x * 128;

    int Keff = K;
    if (CAUSAL_K) { const int kl = (blockIdx.y + 1) * 128; Keff = kl < K ? kl : K; }
    const int nchunk = Keff >> 5;   // K-chunk = 32

    const uint32_t sb = smem_u32(smem);

    // ldmatrix lane geometry
    const int aRowSel = ((lane >> 3) & 1) * 8 + (lane & 7);  // row within 16
    const int aColSel = (lane >> 4) * 16;                    // 0 or 16 bytes
    const int bRowSel = lane & 7;                            // row within 8
    const int bColSel = ((lane >> 3) & 1) * 16;              // 0 or 16 bytes
    const uint32_t aBase = (uint32_t)((wr * 64 + aRowSel) * ROWB + aColSel);
    const uint32_t bBase = (uint32_t)((wc * 32 + bRowSel) * ROWB + bColSel);

    // loader: per tile, 2 cp.async of 16B per thread (128 rows x 64 B)
    auto ldstage = [&](int c, int s) {
        const long long kofs = (long long)c * 32;
        const uint32_t st = sb + s * STAGE_BYTES;
        const __nv_bfloat16* G[4] = { Ah, Al, Bh, Bl };
        #pragma unroll
        for (int t = 0; t < 4; t++) {
            const int r0 = (t < 2) ? row0 : col0;
            #pragma unroll
            for (int o = 0; o < 2; o++) {
                const int lin = tid + o * 256;
                const int row = lin >> 2;
                const int cb  = (lin & 3) * 16;
                const char* src = (const char*)G[t] + ((size_t)(r0 + row) * K + kofs) * 2 + cb;
                cp_async16(st + t * SM_TILE + row * ROWB + cb, src);
            }
        }
        cp_commit();
    };

    float acc[4][4][4];
    #pragma unroll
    for (int i = 0; i < 4; i++)
        #pragma unroll
        for (int j = 0; j < 4; j++)
            #pragma unroll
            for (int r = 0; r < 4; r++) acc[i][j][r] = 0.0f;

    ldstage(0, 0);
    if (nchunk > 1) ldstage(1, 1); else cp_commit();

    for (int c = 0; c < nchunk; c++) {
        if (c + 2 < nchunk) ldstage(c + 2, (c + 2) % NSTAGE);
        else cp_commit();
        cp_wait<2>();
        __syncthreads();                  // stage c visible

        const uint32_t stg = sb + (c % NSTAGE) * STAGE_BYTES;
        #pragma unroll
        for (int ks = 0; ks < 2; ks++) {
            const uint32_t ko = ks * 32;
            uint32_t bh[4][2], bl[4][2];
            #pragma unroll
            for (int nt = 0; nt < 4; nt++) {
                const uint32_t off = stg + bBase + nt * (8 * ROWB) + ko;
                ldsm_x2(bh[nt], off + 2 * SM_TILE);
                ldsm_x2(bl[nt], off + 3 * SM_TILE);
            }
            #pragma unroll
            for (int mt = 0; mt < 4; mt++) {
                const uint32_t off = stg + aBase + mt * (16 * ROWB) + ko;
                uint32_t ah[4], al[4];
                ldsm_x4(ah, off);
                ldsm_x4(al, off + SM_TILE);
                #pragma unroll
                for (int nt = 0; nt < 4; nt++) {
                    mma16816(acc[mt][nt], ah, bh[nt]);
                    mma16816(acc[mt][nt], ah, bl[nt]);
                    mma16816(acc[mt][nt], al, bh[nt]);
                }
            }
        }
        __syncthreads();                  // before buffer reuse
    }

    // epilogue
    #pragma unroll
    for (int mt = 0; mt < 4; mt++) {
        const int r = row0 + wr * 64 + mt * 16 + r4;
        #pragma unroll
        for (int nt = 0; nt < 4; nt++) {
            const int cidx = col0 + wc * 32 + nt * 8 + c4 * 2;
            float b0 = 0.f, b1 = 0.f;
            if (BIAS) { b0 = __ldg(bias + cidx); b1 = __ldg(bias + cidx + 1); }
            const float v00 = alpha * acc[mt][nt][0] + b0;
            const float v01 = alpha * acc[mt][nt][1] + b1;
            const float v10 = alpha * acc[mt][nt][2] + b0;
            const float v11 = alpha * acc[mt][nt][3] + b1;
            if (OUT_SPLIT) {
                __nv_bfloat16 h0, l0, h1, l1;
                split1(v00, h0, l0); split1(v01, h1, l1);
                *(__nv_bfloat162*)(Ch + (size_t)r * N + cidx) = __nv_bfloat162(h0, h1);
                *(__nv_bfloat162*)(Cl + (size_t)r * N + cidx) = __nv_bfloat162(l0, l1);
                split1(v10, h0, l0); split1(v11, h1, l1);
                *(__nv_bfloat162*)(Ch + (size_t)(r + 8) * N + cidx) = __nv_bfloat162(h0, h1);
                *(__nv_bfloat162*)(Cl + (size_t)(r + 8) * N + cidx) = __nv_bfloat162(l0, l1);
            } else {
                float* Cz = C + (size_t)blockIdx.z * sC;
                *(float2*)(Cz + (size_t)r * N + cidx)       = make_float2(v00, v01);
                *(float2*)(Cz + (size_t)(r + 8) * N + cidx) = make_float2(v10, v11);
            }
        }
    }
}

// ---------------------------------------------------------------------------
// fp32 -> bf16 (hi, lo) elementwise split, float4-vectorized
// ---------------------------------------------------------------------------
__global__ void split_fp32(const float* __restrict__ src,
                           __nv_bfloat16* __restrict__ hi, __nv_bfloat16* __restrict__ lo,
                           long long n4)
{
    const long long i = (long long)blockIdx.x * blockDim.x + threadIdx.x;
    if (i >= n4) return;
    float4 v = ((const float4*)src)[i];
    __nv_bfloat16 h0, h1, h2, h3, l0, l1, l2, l3;
    split1(v.x, h0, l0); split1(v.y, h1, l1); split1(v.z, h2, l2); split1(v.w, h3, l3);
    __nv_bfloat162* H = (__nv_bfloat162*)hi;
    __nv_bfloat162* L = (__nv_bfloat162*)lo;
    H[2 * i]     = __nv_bfloat162(h0, h1);
    H[2 * i + 1] = __nv_bfloat162(h2, h3);
    L[2 * i]     = __nv_bfloat162(l0, l1);
    L[2 * i + 1] = __nv_bfloat162(l2, l3);
}

// ---------------------------------------------------------------------------
// fp32 [R,C] -> transposed bf16 hi/lo [C,R], batched; tiled 32x32
// ---------------------------------------------------------------------------
__global__ void transpose_split(const float* __restrict__ in,
                                __nv_bfloat16* __restrict__ oh, __nv_bfloat16* __restrict__ ol,
                                int R, int C, long long sIn, long long sOut)
{
    __shared__ float t[32][33];
    in += (size_t)blockIdx.z * sIn;
    oh += (size_t)blockIdx.z * sOut;
    ol += (size_t)blockIdx.z * sOut;
    const int c0 = blockIdx.x * 32, r0 = blockIdx.y * 32;
    const int tx = threadIdx.x & 31, ty = threadIdx.x >> 5;   // 256 thr: ty 0..7
    #pragma unroll
    for (int k = 0; k < 32; k += 8)
        t[ty + k][tx] = in[(size_t)(r0 + ty + k) * C + c0 + tx];
    __syncthreads();
    #pragma unroll
    for (int k = 0; k < 32; k += 8) {
        __nv_bfloat16 h, l;
        split1(t[tx][ty + k], h, l);
        oh[(size_t)(c0 + ty + k) * R + r0 + tx] = h;
        ol[(size_t)(c0 + ty + k) * R + r0 + tx] = l;
    }
}

// ---------------------------------------------------------------------------
// Masked causal softmax: reads fp32 scores, writes bf16 hi/lo P.
// Padded query rows -> zeros (handled later by scatter_padded).
// ---------------------------------------------------------------------------
__global__ void masked_softmax(const int* __restrict__ mask)
{
    const int q = blockIdx.x;
    const int b = blockIdx.y;
    const size_t off = ((size_t)b * SS + q) * SS;
    const float* row = g_s + off;
    __nv_bfloat16* ph = g_ph + off;
    __nv_bfloat16* pl = g_pl + off;
    const int tid = threadIdx.x;   // 256 threads, 8 elems each

    __shared__ float red[256];

    if (mask[b * SS + q] != 0) {
        #pragma unroll
        for (int it = 0; it < 8; it++) {
            ph[tid + it * 256] = __float2bfloat16(0.0f);
            pl[tid + it * 256] = __float2bfloat16(0.0f);
        }
        return;
    }

    float vals[8];
    float m = -INFINITY;
    #pragma unroll
    for (int it = 0; it < 8; it++) {
        const int k = tid + it * 256;
        const bool valid = (k <= q) && (mask[b * SS + k] == 0);
        const float s = valid ? row[k] : -INFINITY;
        vals[it] = s;
        m = fmaxf(m, s);
    }
    red[tid] = m;
    __syncthreads();
    for (int o = 128; o > 0; o >>= 1) {
        if (tid < o) red[tid] = fmaxf(red[tid], red[tid + o]);
        __syncthreads();
    }
    m = red[0];
    __syncthreads();

    float sum = 0.0f;
    #pragma unroll
    for (int it = 0; it < 8; it++) {
        const float e = (vals[it] == -INFINITY) ? 0.0f : __expf(vals[it] - m);
        vals[it] = e;
        sum += e;
    }
    red[tid] = sum;
    __syncthreads();
    for (int o = 128; o > 0; o >>= 1) {
        if (tid < o) red[tid] += red[tid + o];
        __syncthreads();
    }
    const float inv = 1.0f / red[0];

    #pragma unroll
    for (int it = 0; it < 8; it++) {
        __nv_bfloat16 h, l;
        split1(vals[it] * inv, h, l);
        ph[tid + it * 256] = h;
        pl[tid + it * 256] = l;
    }
}

// ---------------------------------------------------------------------------
__global__ void v_colmean()
{
    const int d = blockIdx.x * 256 + threadIdx.x;
    const int b = blockIdx.y;
    const float* vb = g_v + (size_t)b * SS * DD + d;
    float s = 0.0f;
    for (int k = 0; k < SS; k++) s += vb[(size_t)k * DD];
    g_vmean[b * DD + d] = s * (1.0f / (float)SS);
}

__global__ void scatter_padded(const int* __restrict__ mask, float* __restrict__ out)
{
    const int q = blockIdx.x;
    const int b = blockIdx.y;
    if (mask[b * SS + q] == 0) return;
    const int tid = threadIdx.x;
    float* o = out + ((size_t)b * SS + q) * DD;
    const float* vm = g_vmean + b * DD;
    #pragma unroll
    for (int it = 0; it < 4; it++) o[tid + it * 256] = vm[tid + it * 256];
}

// ---------------------------------------------------------------------------
extern "C" void kernel_launch(void* const* d_in, const int* in_sizes, int n_in,
                              void* d_out, int out_size)
{
    const float* x    = (const float*)d_in[0];
    const int*   mask = (const int*)d_in[1];
    const float* Wq   = (const float*)d_in[2];
    const float* bq   = (const float*)d_in[3];
    const float* Wk   = (const float*)d_in[4];
    const float* bk   = (const float*)d_in[5];
    const float* Wv   = (const float*)d_in[6];
    const float* bv   = (const float*)d_in[7];
    float* out = (float*)d_out;

    cudaFuncSetAttribute(gemm_bf16x3<false, false, true, true>,
                         cudaFuncAttributeMaxDynamicSharedMemorySize, SMEM_BYTES);
    cudaFuncSetAttribute(gemm_bf16x3<false, false, true, false>,
                         cudaFuncAttributeMaxDynamicSharedMemorySize, SMEM_BYTES);
    cudaFuncSetAttribute(gemm_bf16x3<true, false, false, false>,
                         cudaFuncAttributeMaxDynamicSharedMemorySize, SMEM_BYTES);
    cudaFuncSetAttribute(gemm_bf16x3<false, true, false, false>,
                         cudaFuncAttributeMaxDynamicSharedMemorySize, SMEM_BYTES);

    __nv_bfloat16 *xh, *xl, *wqth, *wqtl, *wkth, *wktl, *wvth, *wvtl;
    __nv_bfloat16 *qh, *ql, *kh, *kl, *vth, *vtl, *ph, *pl;
    float *v, *s;
    cudaGetSymbolAddress((void**)&xh, g_xh);     cudaGetSymbolAddress((void**)&xl, g_xl);
    cudaGetSymbolAddress((void**)&wqth, g_wqt_h); cudaGetSymbolAddress((void**)&wqtl, g_wqt_l);
    cudaGetSymbolAddress((void**)&wkth, g_wkt_h); cudaGetSymbolAddress((void**)&wktl, g_wkt_l);
    cudaGetSymbolAddress((void**)&wvth, g_wvt_h); cudaGetSymbolAddress((void**)&wvtl, g_wvt_l);
    cudaGetSymbolAddress((void**)&qh, g_qh);     cudaGetSymbolAddress((void**)&ql, g_ql);
    cudaGetSymbolAddress((void**)&kh, g_kh);     cudaGetSymbolAddress((void**)&kl, g_kl);
    cudaGetSymbolAddress((void**)&v, g_v);
    cudaGetSymbolAddress((void**)&vth, g_vth);   cudaGetSymbolAddress((void**)&vtl, g_vtl);
    cudaGetSymbolAddress((void**)&s, g_s);
    cudaGetSymbolAddress((void**)&ph, g_ph);     cudaGetSymbolAddress((void**)&pl, g_pl);

    const float scale = 1.0f / sqrtf((float)DKK);

    // 1. split x into bf16 hi/lo
    {
        long long n4 = (long long)MTOT * DD / 4;
        split_fp32<<<(unsigned)((n4 + 255) / 256), 256>>>(x, xh, xl, n4);
    }
    // 2. transpose + split weights:  W[K,N] -> WT[N,K]
    transpose_split<<<dim3(DKK / 32, DD / 32, 1), 256>>>(Wq, wqth, wqtl, DD, DKK, 0, 0);
    transpose_split<<<dim3(DKK / 32, DD / 32, 1), 256>>>(Wk, wkth, wktl, DD, DKK, 0, 0);
    transpose_split<<<dim3(DD / 32, DD / 32, 1), 256>>>(Wv, wvth, wvtl, DD, DD, 0, 0);

    // 3. projections: q, k write bf16 hi/lo directly; v stays fp32
    gemm_bf16x3<false, false, true, true><<<dim3(1, MTOT / 128, 1), 256, SMEM_BYTES>>>(
        xh, xl, wqth, wqtl, bq, nullptr, qh, ql, MTOT, DKK, DD, 0, 0, 0, 1.0f);
    gemm_bf16x3<false, false, true, true><<<dim3(1, MTOT / 128, 1), 256, SMEM_BYTES>>>(
        xh, xl, wkth, wktl, bk, nullptr, kh, kl, MTOT, DKK, DD, 0, 0, 0, 1.0f);
    gemm_bf16x3<false, false, true, false><<<dim3(DD / 128, MTOT / 128, 1), 256, SMEM_BYTES>>>(
        xh, xl, wvth, wvtl, bv, v, nullptr, nullptr, MTOT, DD, DD, 0, 0, 0, 1.0f);

    // 4. transpose+split v per batch; V column means
    transpose_split<<<dim3(DD / 32, SS / 32, BB), 256>>>(
        v, vth, vtl, SS, DD, (long long)SS * DD, (long long)SS * DD);
    v_colmean<<<dim3(DD / 256, BB), 256>>>();

    // 5. scores = (q @ k^T) * scale, per batch, lower-triangle tiles only
    gemm_bf16x3<true, false, false, false><<<dim3(SS / 128, SS / 128, BB), 256, SMEM_BYTES>>>(
        qh, ql, kh, kl, nullptr, s, nullptr, nullptr, SS, SS, DKK,
        (long long)SS * DKK, (long long)SS * DKK, (long long)SS * SS, scale);

    // 6. masked softmax -> P (bf16 hi/lo)
    masked_softmax<<<dim3(SS, BB), 256>>>(mask);

    // 7. out = P @ V (V given transposed as [D, S]), K truncated causally
    gemm_bf16x3<false, true, false, false><<<dim3(DD / 128, SS / 128, BB), 256, SMEM_BYTES>>>(
        ph, pl, vth, vtl, nullptr, out, nullptr, nullptr, SS, DD, SS,
        (long long)SS * SS, (long long)DD * SS, (long long)SS * DD, 1.0f);

    // 8. padded rows <- uniform attention (V column mean)
    scatter_padded<<<dim3(SS, BB), 256>>>(mask, out);
}

// round 7
// speedup vs baseline: 2.6806x; 1.0025x over previous
#include <cuda_runtime.h>
#include <cuda_bf16.h>
#include <math.h>
#include <stdint.h>

#define BB 4
#define SS 2048
#define DD 1024
#define DKK 128
#define MTOT (BB * SS)   // 8192

// ---------------------------------------------------------------------------
// Device scratch (allocation-free per harness rules)
// ---------------------------------------------------------------------------
__device__ __nv_bfloat16 g_xh[(size_t)MTOT * DD];
__device__ __nv_bfloat16 g_xl[(size_t)MTOT * DD];
__device__ __nv_bfloat16 g_wqt_h[DKK * DD], g_wqt_l[DKK * DD];
__device__ __nv_bfloat16 g_wkt_h[DKK * DD], g_wkt_l[DKK * DD];
__device__ __nv_bfloat16 g_wvt_h[DD * DD],  g_wvt_l[DD * DD];
__device__ __nv_bfloat16 g_qh[(size_t)MTOT * DKK], g_ql[(size_t)MTOT * DKK];
__device__ __nv_bfloat16 g_kh[(size_t)MTOT * DKK], g_kl[(size_t)MTOT * DKK];
__device__ float g_v[(size_t)MTOT * DD];
__device__ __nv_bfloat16 g_vth[(size_t)BB * DD * SS], g_vtl[(size_t)BB * DD * SS];
__device__ float g_s[(size_t)BB * SS * SS];
__device__ __nv_bfloat16 g_ph[(size_t)BB * SS * SS], g_pl[(size_t)BB * SS * SS];
__device__ float g_vmean[BB * DD];

// ---------------------------------------------------------------------------
// mma.sync + cp.async + ldmatrix helpers (plain compute_103-safe PTX)
// ---------------------------------------------------------------------------
__device__ __forceinline__ uint32_t smem_u32(const void* p) {
    uint32_t a;
    asm("{ .reg .u64 t; cvta.to.shared.u64 t, %1; cvt.u32.u64 %0, t; }"
        : "=r"(a) : "l"(p));
    return a;
}
__device__ __forceinline__ void cp_async16(uint32_t dst, const void* src) {
    asm volatile("cp.async.cg.shared.global [%0], [%1], 16;"
                 :: "r"(dst), "l"(src) : "memory");
}
__device__ __forceinline__ void cp_commit() {
    asm volatile("cp.async.commit_group;" ::: "memory");
}
template<int N>
__device__ __forceinline__ void cp_wait() {
    asm volatile("cp.async.wait_group %0;" :: "n"(N) : "memory");
}
__device__ __forceinline__ void mma16816(float* c, const uint32_t* a, const uint32_t* b) {
    asm volatile(
        "mma.sync.aligned.m16n8k16.row.col.f32.bf16.bf16.f32 "
        "{%0,%1,%2,%3}, {%4,%5,%6,%7}, {%8,%9}, {%0,%1,%2,%3};"
        : "+f"(c[0]), "+f"(c[1]), "+f"(c[2]), "+f"(c[3])
        : "r"(a[0]), "r"(a[1]), "r"(a[2]), "r"(a[3]), "r"(b[0]), "r"(b[1]));
}
__device__ __forceinline__ void ldsm_x4(uint32_t* r, uint32_t addr) {
    asm volatile("ldmatrix.sync.aligned.m8n8.x4.shared.b16 {%0,%1,%2,%3}, [%4];"
                 : "=r"(r[0]), "=r"(r[1]), "=r"(r[2]), "=r"(r[3]) : "r"(addr));
}
__device__ __forceinline__ void ldsm_x2(uint32_t* r, uint32_t addr) {
    asm volatile("ldmatrix.sync.aligned.m8n8.x2.shared.b16 {%0,%1}, [%2];"
                 : "=r"(r[0]), "=r"(r[1]) : "r"(addr));
}

__device__ __forceinline__ void split1(float x, __nv_bfloat16& h, __nv_bfloat16& l) {
    h = __float2bfloat16(x);
    l = __float2bfloat16(x - __bfloat162float(h));
}

// ---------------------------------------------------------------------------
// bf16x3 GEMM on HMMA (mma.sync + ldmatrix), ILP-ordered MMA issue.
// C[M,N] = alpha*(A @ B^T) (+ bias);  A bf16 (hi,lo) [M,K], B bf16 (hi,lo)
// [N,K], both K-major.  CTA tile 128x128, warp tile 64x32, K-chunk 32,
// 3-stage cp.async pipeline.  SMEM row stride 80 B (conflict-free).
// ---------------------------------------------------------------------------
#define ROWB 80
#define SM_TILE (128 * ROWB)            // 10240
#define STAGE_BYTES (4 * SM_TILE)       // 40960: Ah, Al, Bh, Bl
#define NSTAGE 3
#define SMEM_BYTES (NSTAGE * STAGE_BYTES)  // 122880

template<bool SKIP_UPPER, bool CAUSAL_K, bool BIAS, bool OUT_SPLIT>
__global__ void __launch_bounds__(256, 1)
gemm_bf16x3(const __nv_bfloat16* __restrict__ Ah, const __nv_bfloat16* __restrict__ Al,
            const __nv_bfloat16* __restrict__ Bh, const __nv_bfloat16* __restrict__ Bl,
            const float* __restrict__ bias, float* __restrict__ C,
            __nv_bfloat16* __restrict__ Ch, __nv_bfloat16* __restrict__ Cl,
            int M, int N, int K,
            long long sA, long long sB, long long sC, float alpha)
{
    if (SKIP_UPPER && blockIdx.x > blockIdx.y) return;
    extern __shared__ char smem[];

    const int tid = threadIdx.x;
    const int wid = tid >> 5, lane = tid & 31;
    const int wr = wid >> 2;        // 0..1  warp row (64 rows)
    const int wc = wid & 3;         // 0..3  warp col (32 cols)
    const int r4 = lane >> 2;       // 0..7
    const int c4 = lane & 3;        // 0..3

    Ah += (size_t)blockIdx.z * sA;  Al += (size_t)blockIdx.z * sA;
    Bh += (size_t)blockIdx.z * sB;  Bl += (size_t)blockIdx.z * sB;

    const int row0 = blockIdx.y * 128;
    const int col0 = blockIdx.x * 128;

    int Keff = K;
    if (CAUSAL_K) { const int kl = (blockIdx.y + 1) * 128; Keff = kl < K ? kl : K; }
    const int nchunk = Keff >> 5;   // K-chunk = 32

    const uint32_t sb = smem_u32(smem);

    // ldmatrix lane geometry
    const int aRowSel = ((lane >> 3) & 1) * 8 + (lane & 7);  // row within 16
    const int aColSel = (lane >> 4) * 16;                    // 0 or 16 bytes
    const int bRowSel = lane & 7;                            // row within 8
    const int bColSel = ((lane >> 3) & 1) * 16;              // 0 or 16 bytes
    const uint32_t aBase = (uint32_t)((wr * 64 + aRowSel) * ROWB + aColSel);
    const uint32_t bBase = (uint32_t)((wc * 32 + bRowSel) * ROWB + bColSel);

    // loader: per tile, 2 cp.async of 16B per thread (128 rows x 64 B)
    auto ldstage = [&](int c, int s) {
        const long long kofs = (long long)c * 32;
        const uint32_t st = sb + s * STAGE_BYTES;
        const __nv_bfloat16* G[4] = { Ah, Al, Bh, Bl };
        #pragma unroll
        for (int t = 0; t < 4; t++) {
            const int r0 = (t < 2) ? row0 : col0;
            #pragma unroll
            for (int o = 0; o < 2; o++) {
                const int lin = tid + o * 256;
                const int row = lin >> 2;
                const int cb  = (lin & 3) * 16;
                const char* src = (const char*)G[t] + ((size_t)(r0 + row) * K + kofs) * 2 + cb;
                cp_async16(st + t * SM_TILE + row * ROWB + cb, src);
            }
        }
        cp_commit();
    };

    float acc[4][4][4];
    #pragma unroll
    for (int i = 0; i < 4; i++)
        #pragma unroll
        for (int j = 0; j < 4; j++)
            #pragma unroll
            for (int r = 0; r < 4; r++) acc[i][j][r] = 0.0f;

    ldstage(0, 0);
    if (nchunk > 1) ldstage(1, 1); else cp_commit();

    for (int c = 0; c < nchunk; c++) {
        if (c + 2 < nchunk) ldstage(c + 2, (c + 2) % NSTAGE);
        else cp_commit();
        cp_wait<2>();
        __syncthreads();                  // stage c visible

        const uint32_t stg = sb + (c % NSTAGE) * STAGE_BYTES;
        #pragma unroll
        for (int ks = 0; ks < 2; ks++) {
            const uint32_t ko = ks * 32;

            // load ALL fragments first
            uint32_t ah[4][4], al[4][4], bh[4][2], bl[4][2];
            #pragma unroll
            for (int nt = 0; nt < 4; nt++) {
                const uint32_t off = stg + bBase + nt * (8 * ROWB) + ko;
                ldsm_x2(bh[nt], off + 2 * SM_TILE);
                ldsm_x2(bl[nt], off + 3 * SM_TILE);
            }
            #pragma unroll
            for (int mt = 0; mt < 4; mt++) {
                const uint32_t off = stg + aBase + mt * (16 * ROWB) + ko;
                ldsm_x4(ah[mt], off);
                ldsm_x4(al[mt], off + SM_TILE);
            }

            // product-major issue: dependent MMAs on the same accumulator are
            // 16 instructions apart -> HMMA latency fully hidden by ILP
            #pragma unroll
            for (int mt = 0; mt < 4; mt++)
                #pragma unroll
                for (int nt = 0; nt < 4; nt++)
                    mma16816(acc[mt][nt], ah[mt], bh[nt]);
            #pragma unroll
            for (int mt = 0; mt < 4; mt++)
                #pragma unroll
                for (int nt = 0; nt < 4; nt++)
                    mma16816(acc[mt][nt], ah[mt], bl[nt]);
            #pragma unroll
            for (int mt = 0; mt < 4; mt++)
                #pragma unroll
                for (int nt = 0; nt < 4; nt++)
                    mma16816(acc[mt][nt], al[mt], bh[nt]);
        }
        __syncthreads();                  // before buffer reuse
    }

    // epilogue
    #pragma unroll
    for (int mt = 0; mt < 4; mt++) {
        const int r = row0 + wr * 64 + mt * 16 + r4;
        #pragma unroll
        for (int nt = 0; nt < 4; nt++) {
            const int cidx = col0 + wc * 32 + nt * 8 + c4 * 2;
            float b0 = 0.f, b1 = 0.f;
            if (BIAS) { b0 = __ldg(bias + cidx); b1 = __ldg(bias + cidx + 1); }
            const float v00 = alpha * acc[mt][nt][0] + b0;
            const float v01 = alpha * acc[mt][nt][1] + b1;
            const float v10 = alpha * acc[mt][nt][2] + b0;
            const float v11 = alpha * acc[mt][nt][3] + b1;
            if (OUT_SPLIT) {
                __nv_bfloat16 h0, l0, h1, l1;
                split1(v00, h0, l0); split1(v01, h1, l1);
                *(__nv_bfloat162*)(Ch + (size_t)r * N + cidx) = __nv_bfloat162(h0, h1);
                *(__nv_bfloat162*)(Cl + (size_t)r * N + cidx) = __nv_bfloat162(l0, l1);
                split1(v10, h0, l0); split1(v11, h1, l1);
                *(__nv_bfloat162*)(Ch + (size_t)(r + 8) * N + cidx) = __nv_bfloat162(h0, h1);
                *(__nv_bfloat162*)(Cl + (size_t)(r + 8) * N + cidx) = __nv_bfloat162(l0, l1);
            } else {
                float* Cz = C + (size_t)blockIdx.z * sC;
                *(float2*)(Cz + (size_t)r * N + cidx)       = make_float2(v00, v01);
                *(float2*)(Cz + (size_t)(r + 8) * N + cidx) = make_float2(v10, v11);
            }
        }
    }
}

// ---------------------------------------------------------------------------
// fp32 -> bf16 (hi, lo) elementwise split, float4-vectorized
// ---------------------------------------------------------------------------
__global__ void split_fp32(const float* __restrict__ src,
                           __nv_bfloat16* __restrict__ hi, __nv_bfloat16* __restrict__ lo,
                           long long n4)
{
    const long long i = (long long)blockIdx.x * blockDim.x + threadIdx.x;
    if (i >= n4) return;
    float4 v = ((const float4*)src)[i];
    __nv_bfloat16 h0, h1, h2, h3, l0, l1, l2, l3;
    split1(v.x, h0, l0); split1(v.y, h1, l1); split1(v.z, h2, l2); split1(v.w, h3, l3);
    __nv_bfloat162* H = (__nv_bfloat162*)hi;
    __nv_bfloat162* L = (__nv_bfloat162*)lo;
    H[2 * i]     = __nv_bfloat162(h0, h1);
    H[2 * i + 1] = __nv_bfloat162(h2, h3);
    L[2 * i]     = __nv_bfloat162(l0, l1);
    L[2 * i + 1] = __nv_bfloat162(l2, l3);
}

// ---------------------------------------------------------------------------
// fp32 [R,C] -> transposed bf16 hi/lo [C,R], batched; tiled 32x32
// ---------------------------------------------------------------------------
__global__ void transpose_split(const float* __restrict__ in,
                                __nv_bfloat16* __restrict__ oh, __nv_bfloat16* __restrict__ ol,
                                int R, int C, long long sIn, long long sOut)
{
    __shared__ float t[32][33];
    in += (size_t)blockIdx.z * sIn;
    oh += (size_t)blockIdx.z * sOut;
    ol += (size_t)blockIdx.z * sOut;
    const int c0 = blockIdx.x * 32, r0 = blockIdx.y * 32;
    const int tx = threadIdx.x & 31, ty = threadIdx.x >> 5;   // 256 thr: ty 0..7
    #pragma unroll
    for (int k = 0; k < 32; k += 8)
        t[ty + k][tx] = in[(size_t)(r0 + ty + k) * C + c0 + tx];
    __syncthreads();
    #pragma unroll
    for (int k = 0; k < 32; k += 8) {
        __nv_bfloat16 h, l;
        split1(t[tx][ty + k], h, l);
        oh[(size_t)(c0 + ty + k) * R + r0 + tx] = h;
        ol[(size_t)(c0 + ty + k) * R + r0 + tx] = l;
    }
}

// ---------------------------------------------------------------------------
// Masked causal softmax: reads fp32 scores, writes bf16 hi/lo P.
// Padded query rows -> zeros (handled later by scatter_padded).
// ---------------------------------------------------------------------------
__global__ void masked_softmax(const int* __restrict__ mask)
{
    const int q = blockIdx.x;
    const int b = blockIdx.y;
    const size_t off = ((size_t)b * SS + q) * SS;
    const float* row = g_s + off;
    __nv_bfloat16* ph = g_ph + off;
    __nv_bfloat16* pl = g_pl + off;
    const int tid = threadIdx.x;   // 256 threads, 8 elems each

    __shared__ float red[256];

    if (mask[b * SS + q] != 0) {
        #pragma unroll
        for (int it = 0; it < 8; it++) {
            ph[tid + it * 256] = __float2bfloat16(0.0f);
            pl[tid + it * 256] = __float2bfloat16(0.0f);
        }
        return;
    }

    float vals[8];
    float m = -INFINITY;
    #pragma unroll
    for (int it = 0; it < 8; it++) {
        const int k = tid + it * 256;
        const bool valid = (k <= q) && (mask[b * SS + k] == 0);
        const float s = valid ? row[k] : -INFINITY;
        vals[it] = s;
        m = fmaxf(m, s);
    }
    red[tid] = m;
    __syncthreads();
    for (int o = 128; o > 0; o >>= 1) {
        if (tid < o) red[tid] = fmaxf(red[tid], red[tid + o]);
        __syncthreads();
    }
    m = red[0];
    __syncthreads();

    float sum = 0.0f;
    #pragma unroll
    for (int it = 0; it < 8; it++) {
        const float e = (vals[it] == -INFINITY) ? 0.0f : __expf(vals[it] - m);
        vals[it] = e;
        sum += e;
    }
    red[tid] = sum;
    __syncthreads();
    for (int o = 128; o > 0; o >>= 1) {
        if (tid < o) red[tid] += red[tid + o];
        __syncthreads();
    }
    const float inv = 1.0f / red[0];

    #pragma unroll
    for (int it = 0; it < 8; it++) {
        __nv_bfloat16 h, l;
        split1(vals[it] * inv, h, l);
        ph[tid + it * 256] = h;
        pl[tid + it * 256] = l;
    }
}

// ---------------------------------------------------------------------------
__global__ void v_colmean()
{
    const int d = blockIdx.x * 256 + threadIdx.x;
    const int b = blockIdx.y;
    const float* vb = g_v + (size_t)b * SS * DD + d;
    float s = 0.0f;
    for (int k = 0; k < SS; k++) s += vb[(size_t)k * DD];
    g_vmean[b * DD + d] = s * (1.0f / (float)SS);
}

__global__ void scatter_padded(const int* __restrict__ mask, float* __restrict__ out)
{
    const int q = blockIdx.x;
    const int b = blockIdx.y;
    if (mask[b * SS + q] == 0) return;
    const int tid = threadIdx.x;
    float* o = out + ((size_t)b * SS + q) * DD;
    const float* vm = g_vmean + b * DD;
    #pragma unroll
    for (int it = 0; it < 4; it++) o[tid + it * 256] = vm[tid + it * 256];
}

// ---------------------------------------------------------------------------
extern "C" void kernel_launch(void* const* d_in, const int* in_sizes, int n_in,
                              void* d_out, int out_size)
{
    const float* x    = (const float*)d_in[0];
    const int*   mask = (const int*)d_in[1];
    const float* Wq   = (const float*)d_in[2];
    const float* bq   = (const float*)d_in[3];
    const float* Wk   = (const float*)d_in[4];
    const float* bk   = (const float*)d_in[5];
    const float* Wv   = (const float*)d_in[6];
    const float* bv   = (const float*)d_in[7];
    float* out = (float*)d_out;

    cudaFuncSetAttribute(gemm_bf16x3<false, false, true, true>,
                         cudaFuncAttributeMaxDynamicSharedMemorySize, SMEM_BYTES);
    cudaFuncSetAttribute(gemm_bf16x3<false, false, true, false>,
                         cudaFuncAttributeMaxDynamicSharedMemorySize, SMEM_BYTES);
    cudaFuncSetAttribute(gemm_bf16x3<true, false, false, false>,
                         cudaFuncAttributeMaxDynamicSharedMemorySize, SMEM_BYTES);
    cudaFuncSetAttribute(gemm_bf16x3<false, true, false, false>,
                         cudaFuncAttributeMaxDynamicSharedMemorySize, SMEM_BYTES);

    __nv_bfloat16 *xh, *xl, *wqth, *wqtl, *wkth, *wktl, *wvth, *wvtl;
    __nv_bfloat16 *qh, *ql, *kh, *kl, *vth, *vtl, *ph, *pl;
    float *v, *s;
    cudaGetSymbolAddress((void**)&xh, g_xh);     cudaGetSymbolAddress((void**)&xl, g_xl);
    cudaGetSymbolAddress((void**)&wqth, g_wqt_h); cudaGetSymbolAddress((void**)&wqtl, g_wqt_l);
    cudaGetSymbolAddress((void**)&wkth, g_wkt_h); cudaGetSymbolAddress((void**)&wktl, g_wkt_l);
    cudaGetSymbolAddress((void**)&wvth, g_wvt_h); cudaGetSymbolAddress((void**)&wvtl, g_wvt_l);
    cudaGetSymbolAddress((void**)&qh, g_qh);     cudaGetSymbolAddress((void**)&ql, g_ql);
    cudaGetSymbolAddress((void**)&kh, g_kh);     cudaGetSymbolAddress((void**)&kl, g_kl);
    cudaGetSymbolAddress((void**)&v, g_v);
    cudaGetSymbolAddress((void**)&vth, g_vth);   cudaGetSymbolAddress((void**)&vtl, g_vtl);
    cudaGetSymbolAddress((void**)&s, g_s);
    cudaGetSymbolAddress((void**)&ph, g_ph);     cudaGetSymbolAddress((void**)&pl, g_pl);

    const float scale = 1.0f / sqrtf((float)DKK);

    // 1. split x into bf16 hi/lo
    {
        long long n4 = (long long)MTOT * DD / 4;
        split_fp32<<<(unsigned)((n4 + 255) / 256), 256>>>(x, xh, xl, n4);
    }
    // 2. transpose + split weights:  W[K,N] -> WT[N,K]
    transpose_split<<<dim3(DKK / 32, DD / 32, 1), 256>>>(Wq, wqth, wqtl, DD, DKK, 0, 0);
    transpose_split<<<dim3(DKK / 32, DD / 32, 1), 256>>>(Wk, wkth, wktl, DD, DKK, 0, 0);
    transpose_split<<<dim3(DD / 32, DD / 32, 1), 256>>>(Wv, wvth, wvtl, DD, DD, 0, 0);

    // 3. projections: q, k write bf16 hi/lo directly; v stays fp32
    gemm_bf16x3<false, false, true, true><<<dim3(1, MTOT / 128, 1), 256, SMEM_BYTES>>>(
        xh, xl, wqth, wqtl, bq, nullptr, qh, ql, MTOT, DKK, DD, 0, 0, 0, 1.0f);
    gemm_bf16x3<false, false, true, true><<<dim3(1, MTOT / 128, 1), 256, SMEM_BYTES>>>(
        xh, xl, wkth, wktl, bk, nullptr, kh, kl, MTOT, DKK, DD, 0, 0, 0, 1.0f);
    gemm_bf16x3<false, false, true, false><<<dim3(DD / 128, MTOT / 128, 1), 256, SMEM_BYTES>>>(
        xh, xl, wvth, wvtl, bv, v, nullptr, nullptr, MTOT, DD, DD, 0, 0, 0, 1.0f);

    // 4. transpose+split v per batch; V column means
    transpose_split<<<dim3(DD / 32, SS / 32, BB), 256>>>(
        v, vth, vtl, SS, DD, (long long)SS * DD, (long long)SS * DD);
    v_colmean<<<dim3(DD / 256, BB), 256>>>();

    // 5. scores = (q @ k^T) * scale, per batch, lower-triangle tiles only
    gemm_bf16x3<true, false, false, false><<<dim3(SS / 128, SS / 128, BB), 256, SMEM_BYTES>>>(
        qh, ql, kh, kl, nullptr, s, nullptr, nullptr, SS, SS, DKK,
        (long long)SS * DKK, (long long)SS * DKK, (long long)SS * SS, scale);

    // 6. masked softmax -> P (bf16 hi/lo)
    masked_softmax<<<dim3(SS, BB), 256>>>(mask);

    // 7. out = P @ V (V given transposed as [D, S]), K truncated causally
    gemm_bf16x3<false, true, false, false><<<dim3(DD / 128, SS / 128, BB), 256, SMEM_BYTES>>>(
        ph, pl, vth, vtl, nullptr, out, nullptr, nullptr, SS, DD, SS,
        (long long)SS * SS, (long long)DD * SS, (long long)SS * DD, 1.0f);

    // 8. padded rows <- uniform attention (V column mean)
    scatter_padded<<<dim3(SS, BB), 256>>>(mask, out);
}

// round 8
// speedup vs baseline: 2.8372x; 1.0584x over previous
#include <cuda_runtime.h>
#include <cuda_bf16.h>
#include <math.h>
#include <stdint.h>

#define BB 4
#define SS 2048
#define DD 1024
#define DKK 128
#define MTOT (BB * SS)   // 8192

// ---------------------------------------------------------------------------
// Device scratch (allocation-free per harness rules)
// ---------------------------------------------------------------------------
__device__ __nv_bfloat16 g_xh[(size_t)MTOT * DD];
__device__ __nv_bfloat16 g_xl[(size_t)MTOT * DD];
__device__ __nv_bfloat16 g_wqt_h[DKK * DD], g_wqt_l[DKK * DD];
__device__ __nv_bfloat16 g_wkt_h[DKK * DD], g_wkt_l[DKK * DD];
__device__ __nv_bfloat16 g_wvt_h[DD * DD],  g_wvt_l[DD * DD];
__device__ __nv_bfloat16 g_qh[(size_t)MTOT * DKK], g_ql[(size_t)MTOT * DKK];
__device__ __nv_bfloat16 g_kh[(size_t)MTOT * DKK], g_kl[(size_t)MTOT * DKK];
__device__ float g_v[(size_t)MTOT * DD];
__device__ __nv_bfloat16 g_vth[(size_t)BB * DD * SS], g_vtl[(size_t)BB * DD * SS];
__device__ float g_s[(size_t)BB * SS * SS];
__device__ __nv_bfloat16 g_ph[(size_t)BB * SS * SS], g_pl[(size_t)BB * SS * SS];
__device__ float g_vmean[BB * DD];
__device__ int   g_len[BB];

// ---------------------------------------------------------------------------
// mma.sync + cp.async + ldmatrix helpers (plain compute_103-safe PTX)
// ---------------------------------------------------------------------------
__device__ __forceinline__ uint32_t smem_u32(const void* p) {
    uint32_t a;
    asm("{ .reg .u64 t; cvta.to.shared.u64 t, %1; cvt.u32.u64 %0, t; }"
        : "=r"(a) : "l"(p));
    return a;
}
__device__ __forceinline__ void cp_async16(uint32_t dst, const void* src) {
    asm volatile("cp.async.cg.shared.global [%0], [%1], 16;"
                 :: "r"(dst), "l"(src) : "memory");
}
__device__ __forceinline__ void cp_commit() {
    asm volatile("cp.async.commit_group;" ::: "memory");
}
template<int N>
__device__ __forceinline__ void cp_wait() {
    asm volatile("cp.async.wait_group %0;" :: "n"(N) : "memory");
}
__device__ __forceinline__ void mma16816(float* c, const uint32_t* a, const uint32_t* b) {
    asm volatile(
        "mma.sync.aligned.m16n8k16.row.col.f32.bf16.bf16.f32 "
        "{%0,%1,%2,%3}, {%4,%5,%6,%7}, {%8,%9}, {%0,%1,%2,%3};"
        : "+f"(c[0]), "+f"(c[1]), "+f"(c[2]), "+f"(c[3])
        : "r"(a[0]), "r"(a[1]), "r"(a[2]), "r"(a[3]), "r"(b[0]), "r"(b[1]));
}
__device__ __forceinline__ void ldsm_x4(uint32_t* r, uint32_t addr) {
    asm volatile("ldmatrix.sync.aligned.m8n8.x4.shared.b16 {%0,%1,%2,%3}, [%4];"
                 : "=r"(r[0]), "=r"(r[1]), "=r"(r[2]), "=r"(r[3]) : "r"(addr));
}
__device__ __forceinline__ void ldsm_x2(uint32_t* r, uint32_t addr) {
    asm volatile("ldmatrix.sync.aligned.m8n8.x2.shared.b16 {%0,%1}, [%2];"
                 : "=r"(r[0]), "=r"(r[1]) : "r"(addr));
}

__device__ __forceinline__ void split1(float x, __nv_bfloat16& h, __nv_bfloat16& l) {
    h = __float2bfloat16(x);
    l = __float2bfloat16(x - __bfloat162float(h));
}

// ---------------------------------------------------------------------------
// bf16x3 GEMM on HMMA (mma.sync + ldmatrix), length-aware tile skipping.
// C[M,N] = alpha*(A @ B^T) (+ bias);  A bf16 (hi,lo) [M,K], B bf16 (hi,lo)
// [N,K], both K-major.  CTA tile 128x128, warp tile 64x32, K-chunk 32,
// 3-stage cp.async pipeline.  SMEM row stride 80 B (conflict-free).
//
// LENMODE: 0 none
//          1 projections, batch folded into M (2048 rows/batch):
//              skip tile if (row0 % 2048) >= len[b]
//          2 scores (batch = blockIdx.z): skip if row0 >= len || col0 >= len
//          3 P.V    (batch = blockIdx.z): skip if row0 >= len;
//              Keff = min(causal, round_up(len, 32))
// ---------------------------------------------------------------------------
#define ROWB 80
#define SM_TILE (128 * ROWB)            // 10240
#define STAGE_BYTES (4 * SM_TILE)       // 40960: Ah, Al, Bh, Bl
#define NSTAGE 3
#define SMEM_BYTES (NSTAGE * STAGE_BYTES)  // 122880

template<bool SKIP_UPPER, bool CAUSAL_K, bool BIAS, bool OUT_SPLIT, int LENMODE>
__global__ void __launch_bounds__(256, 1)
gemm_bf16x3(const __nv_bfloat16* __restrict__ Ah, const __nv_bfloat16* __restrict__ Al,
            const __nv_bfloat16* __restrict__ Bh, const __nv_bfloat16* __restrict__ Bl,
            const float* __restrict__ bias, float* __restrict__ C,
            __nv_bfloat16* __restrict__ Ch, __nv_bfloat16* __restrict__ Cl,
            int M, int N, int K,
            long long sA, long long sB, long long sC, float alpha)
{
    if (SKIP_UPPER && blockIdx.x > blockIdx.y) return;

    const int row0 = blockIdx.y * 128;
    const int col0 = blockIdx.x * 128;

    int Keff = K;
    if (CAUSAL_K) { const int kl = (blockIdx.y + 1) * 128; Keff = kl < K ? kl : K; }

    if (LENMODE == 1) {
        const int b = row0 >> 11;                  // 2048 rows per batch
        if ((row0 & 2047) >= g_len[b]) return;
    } else if (LENMODE == 2) {
        const int L = g_len[blockIdx.z];
        if (row0 >= L || col0 >= L) return;
    } else if (LENMODE == 3) {
        const int L = g_len[blockIdx.z];
        if (row0 >= L) return;
        const int kcap = (L + 31) & ~31;
        if (kcap < Keff) Keff = kcap;
    }
    const int nchunk = Keff >> 5;   // K-chunk = 32

    extern __shared__ char smem[];

    const int tid = threadIdx.x;
    const int wid = tid >> 5, lane = tid & 31;
    const int wr = wid >> 2;        // 0..1  warp row (64 rows)
    const int wc = wid & 3;         // 0..3  warp col (32 cols)
    const int r4 = lane >> 2;       // 0..7
    const int c4 = lane & 3;        // 0..3

    Ah += (size_t)blockIdx.z * sA;  Al += (size_t)blockIdx.z * sA;
    Bh += (size_t)blockIdx.z * sB;  Bl += (size_t)blockIdx.z * sB;

    const uint32_t sb = smem_u32(smem);

    // ldmatrix lane geometry
    const int aRowSel = ((lane >> 3) & 1) * 8 + (lane & 7);  // row within 16
    const int aColSel = (lane >> 4) * 16;                    // 0 or 16 bytes
    const int bRowSel = lane & 7;                            // row within 8
    const int bColSel = ((lane >> 3) & 1) * 16;              // 0 or 16 bytes
    const uint32_t aBase = (uint32_t)((wr * 64 + aRowSel) * ROWB + aColSel);
    const uint32_t bBase = (uint32_t)((wc * 32 + bRowSel) * ROWB + bColSel);

    // loader: per tile, 2 cp.async of 16B per thread (128 rows x 64 B)
    auto ldstage = [&](int c, int s) {
        const long long kofs = (long long)c * 32;
        const uint32_t st = sb + s * STAGE_BYTES;
        const __nv_bfloat16* G[4] = { Ah, Al, Bh, Bl };
        #pragma unroll
        for (int t = 0; t < 4; t++) {
            const int r0 = (t < 2) ? row0 : col0;
            #pragma unroll
            for (int o = 0; o < 2; o++) {
                const int lin = tid + o * 256;
                const int row = lin >> 2;
                const int cb  = (lin & 3) * 16;
                const char* src = (const char*)G[t] + ((size_t)(r0 + row) * K + kofs) * 2 + cb;
                cp_async16(st + t * SM_TILE + row * ROWB + cb, src);
            }
        }
        cp_commit();
    };

    float acc[4][4][4];
    #pragma unroll
    for (int i = 0; i < 4; i++)
        #pragma unroll
        for (int j = 0; j < 4; j++)
            #pragma unroll
            for (int r = 0; r < 4; r++) acc[i][j][r] = 0.0f;

    ldstage(0, 0);
    if (nchunk > 1) ldstage(1, 1); else cp_commit();

    for (int c = 0; c < nchunk; c++) {
        if (c + 2 < nchunk) ldstage(c + 2, (c + 2) % NSTAGE);
        else cp_commit();
        cp_wait<2>();
        __syncthreads();                  // stage c visible

        const uint32_t stg = sb + (c % NSTAGE) * STAGE_BYTES;
        #pragma unroll
        for (int ks = 0; ks < 2; ks++) {
            const uint32_t ko = ks * 32;

            // load ALL fragments first
            uint32_t ah[4][4], al[4][4], bh[4][2], bl[4][2];
            #pragma unroll
            for (int nt = 0; nt < 4; nt++) {
                const uint32_t off = stg + bBase + nt * (8 * ROWB) + ko;
                ldsm_x2(bh[nt], off + 2 * SM_TILE);
                ldsm_x2(bl[nt], off + 3 * SM_TILE);
            }
            #pragma unroll
            for (int mt = 0; mt < 4; mt++) {
                const uint32_t off = stg + aBase + mt * (16 * ROWB) + ko;
                ldsm_x4(ah[mt], off);
                ldsm_x4(al[mt], off + SM_TILE);
            }

            // product-major issue: dependent MMAs 16 issues apart
            #pragma unroll
            for (int mt = 0; mt < 4; mt++)
                #pragma unroll
                for (int nt = 0; nt < 4; nt++)
                    mma16816(acc[mt][nt], ah[mt], bh[nt]);
            #pragma unroll
            for (int mt = 0; mt < 4; mt++)
                #pragma unroll
                for (int nt = 0; nt < 4; nt++)
                    mma16816(acc[mt][nt], ah[mt], bl[nt]);
            #pragma unroll
            for (int mt = 0; mt < 4; mt++)
                #pragma unroll
                for (int nt = 0; nt < 4; nt++)
                    mma16816(acc[mt][nt], al[mt], bh[nt]);
        }
        __syncthreads();                  // before buffer reuse
    }

    // epilogue
    #pragma unroll
    for (int mt = 0; mt < 4; mt++) {
        const int r = row0 + wr * 64 + mt * 16 + r4;
        #pragma unroll
        for (int nt = 0; nt < 4; nt++) {
            const int cidx = col0 + wc * 32 + nt * 8 + c4 * 2;
            float b0 = 0.f, b1 = 0.f;
            if (BIAS) { b0 = __ldg(bias + cidx); b1 = __ldg(bias + cidx + 1); }
            const float v00 = alpha * acc[mt][nt][0] + b0;
            const float v01 = alpha * acc[mt][nt][1] + b1;
            const float v10 = alpha * acc[mt][nt][2] + b0;
            const float v11 = alpha * acc[mt][nt][3] + b1;
            if (OUT_SPLIT) {
                __nv_bfloat16 h0, l0, h1, l1;
                split1(v00, h0, l0); split1(v01, h1, l1);
                *(__nv_bfloat162*)(Ch + (size_t)r * N + cidx) = __nv_bfloat162(h0, h1);
                *(__nv_bfloat162*)(Cl + (size_t)r * N + cidx) = __nv_bfloat162(l0, l1);
                split1(v10, h0, l0); split1(v11, h1, l1);
                *(__nv_bfloat162*)(Ch + (size_t)(r + 8) * N + cidx) = __nv_bfloat162(h0, h1);
                *(__nv_bfloat162*)(Cl + (size_t)(r + 8) * N + cidx) = __nv_bfloat162(l0, l1);
            } else {
                float* Cz = C + (size_t)blockIdx.z * sC;
                *(float2*)(Cz + (size_t)r * N + cidx)       = make_float2(v00, v01);
                *(float2*)(Cz + (size_t)(r + 8) * N + cidx) = make_float2(v10, v11);
            }
        }
    }
}

// ---------------------------------------------------------------------------
// per-batch valid length: len[b] = SS - sum(mask[b, :])
// ---------------------------------------------------------------------------
__global__ void compute_len(const int* __restrict__ mask)
{
    const int b = blockIdx.x;
    const int tid = threadIdx.x;
    __shared__ int red[256];
    int s = 0;
    for (int k = tid; k < SS; k += 256) s += mask[b * SS + k];
    red[tid] = s;
    __syncthreads();
    for (int o = 128; o > 0; o >>= 1) {
        if (tid < o) red[tid] += red[tid + o];
        __syncthreads();
    }
    if (tid == 0) g_len[b] = SS - red[0];
}

// ---------------------------------------------------------------------------
// fp32 -> bf16 (hi, lo) elementwise split, float4-vectorized
// ---------------------------------------------------------------------------
__global__ void split_fp32(const float* __restrict__ src,
                           __nv_bfloat16* __restrict__ hi, __nv_bfloat16* __restrict__ lo,
                           long long n4)
{
    const long long i = (long long)blockIdx.x * blockDim.x + threadIdx.x;
    if (i >= n4) return;
    float4 v = ((const float4*)src)[i];
    __nv_bfloat16 h0, h1, h2, h3, l0, l1, l2, l3;
    split1(v.x, h0, l0); split1(v.y, h1, l1); split1(v.z, h2, l2); split1(v.w, h3, l3);
    __nv_bfloat162* H = (__nv_bfloat162*)hi;
    __nv_bfloat162* L = (__nv_bfloat162*)lo;
    H[2 * i]     = __nv_bfloat162(h0, h1);
    H[2 * i + 1] = __nv_bfloat162(h2, h3);
    L[2 * i]     = __nv_bfloat162(l0, l1);
    L[2 * i + 1] = __nv_bfloat162(l2, l3);
}

// ---------------------------------------------------------------------------
// fp32 [R,C] -> transposed bf16 hi/lo [C,R], batched; tiled 32x32
// ---------------------------------------------------------------------------
__global__ void transpose_split(const float* __restrict__ in,
                                __nv_bfloat16* __restrict__ oh, __nv_bfloat16* __restrict__ ol,
                                int R, int C, long long sIn, long long sOut)
{
    __shared__ float t[32][33];
    in += (size_t)blockIdx.z * sIn;
    oh += (size_t)blockIdx.z * sOut;
    ol += (size_t)blockIdx.z * sOut;
    const int c0 = blockIdx.x * 32, r0 = blockIdx.y * 32;
    const int tx = threadIdx.x & 31, ty = threadIdx.x >> 5;   // 256 thr: ty 0..7
    #pragma unroll
    for (int k = 0; k < 32; k += 8)
        t[ty + k][tx] = in[(size_t)(r0 + ty + k) * C + c0 + tx];
    __syncthreads();
    #pragma unroll
    for (int k = 0; k < 32; k += 8) {
        __nv_bfloat16 h, l;
        split1(t[tx][ty + k], h, l);
        oh[(size_t)(c0 + ty + k) * R + r0 + tx] = h;
        ol[(size_t)(c0 + ty + k) * R + r0 + tx] = l;
    }
}

// ---------------------------------------------------------------------------
// Masked causal softmax: reads fp32 scores, writes bf16 hi/lo P.
// Padded query rows -> zeros (handled later by scatter_padded).
// ---------------------------------------------------------------------------
__global__ void masked_softmax(const int* __restrict__ mask)
{
    const int q = blockIdx.x;
    const int b = blockIdx.y;
    const size_t off = ((size_t)b * SS + q) * SS;
    const float* row = g_s + off;
    __nv_bfloat16* ph = g_ph + off;
    __nv_bfloat16* pl = g_pl + off;
    const int tid = threadIdx.x;   // 256 threads, 8 elems each

    __shared__ float red[256];

    if (mask[b * SS + q] != 0) {
        #pragma unroll
        for (int it = 0; it < 8; it++) {
            ph[tid + it * 256] = __float2bfloat16(0.0f);
            pl[tid + it * 256] = __float2bfloat16(0.0f);
        }
        return;
    }

    float vals[8];
    float m = -INFINITY;
    #pragma unroll
    for (int it = 0; it < 8; it++) {
        const int k = tid + it * 256;
        const bool valid = (k <= q) && (mask[b * SS + k] == 0);
        const float s = valid ? row[k] : -INFINITY;
        vals[it] = s;
        m = fmaxf(m, s);
    }
    red[tid] = m;
    __syncthreads();
    for (int o = 128; o > 0; o >>= 1) {
        if (tid < o) red[tid] = fmaxf(red[tid], red[tid + o]);
        __syncthreads();
    }
    m = red[0];
    __syncthreads();

    float sum = 0.0f;
    #pragma unroll
    for (int it = 0; it < 8; it++) {
        const float e = (vals[it] == -INFINITY) ? 0.0f : __expf(vals[it] - m);
        vals[it] = e;
        sum += e;
    }
    red[tid] = sum;
    __syncthreads();
    for (int o = 128; o > 0; o >>= 1) {
        if (tid < o) red[tid] += red[tid + o];
        __syncthreads();
    }
    const float inv = 1.0f / red[0];

    #pragma unroll
    for (int it = 0; it < 8; it++) {
        __nv_bfloat16 h, l;
        split1(vals[it] * inv, h, l);
        ph[tid + it * 256] = h;
        pl[tid + it * 256] = l;
    }
}

// ---------------------------------------------------------------------------
__global__ void v_colmean()
{
    const int d = blockIdx.x * 256 + threadIdx.x;
    const int b = blockIdx.y;
    const float* vb = g_v + (size_t)b * SS * DD + d;
    float s = 0.0f;
    for (int k = 0; k < SS; k++) s += vb[(size_t)k * DD];
    g_vmean[b * DD + d] = s * (1.0f / (float)SS);
}

__global__ void scatter_padded(const int* __restrict__ mask, float* __restrict__ out)
{
    const int q = blockIdx.x;
    const int b = blockIdx.y;
    if (mask[b * SS + q] == 0) return;
    const int tid = threadIdx.x;
    float* o = out + ((size_t)b * SS + q) * DD;
    const float* vm = g_vmean + b * DD;
    #pragma unroll
    for (int it = 0; it < 4; it++) o[tid + it * 256] = vm[tid + it * 256];
}

// ---------------------------------------------------------------------------
extern "C" void kernel_launch(void* const* d_in, const int* in_sizes, int n_in,
                              void* d_out, int out_size)
{
    const float* x    = (const float*)d_in[0];
    const int*   mask = (const int*)d_in[1];
    const float* Wq   = (const float*)d_in[2];
    const float* bq   = (const float*)d_in[3];
    const float* Wk   = (const float*)d_in[4];
    const float* bk   = (const float*)d_in[5];
    const float* Wv   = (const float*)d_in[6];
    const float* bv   = (const float*)d_in[7];
    float* out = (float*)d_out;

    cudaFuncSetAttribute(gemm_bf16x3<false, false, true, true, 1>,
                         cudaFuncAttributeMaxDynamicSharedMemorySize, SMEM_BYTES);
    cudaFuncSetAttribute(gemm_bf16x3<false, false, true, false, 0>,
                         cudaFuncAttributeMaxDynamicSharedMemorySize, SMEM_BYTES);
    cudaFuncSetAttribute(gemm_bf16x3<true, false, false, false, 2>,
                         cudaFuncAttributeMaxDynamicSharedMemorySize, SMEM_BYTES);
    cudaFuncSetAttribute(gemm_bf16x3<false, true, false, false, 3>,
                         cudaFuncAttributeMaxDynamicSharedMemorySize, SMEM_BYTES);

    __nv_bfloat16 *xh, *xl, *wqth, *wqtl, *wkth, *wktl, *wvth, *wvtl;
    __nv_bfloat16 *qh, *ql, *kh, *kl, *vth, *vtl, *ph, *pl;
    float *v, *s;
    cudaGetSymbolAddress((void**)&xh, g_xh);     cudaGetSymbolAddress((void**)&xl, g_xl);
    cudaGetSymbolAddress((void**)&wqth, g_wqt_h); cudaGetSymbolAddress((void**)&wqtl, g_wqt_l);
    cudaGetSymbolAddress((void**)&wkth, g_wkt_h); cudaGetSymbolAddress((void**)&wktl, g_wkt_l);
    cudaGetSymbolAddress((void**)&wvth, g_wvt_h); cudaGetSymbolAddress((void**)&wvtl, g_wvt_l);
    cudaGetSymbolAddress((void**)&qh, g_qh);     cudaGetSymbolAddress((void**)&ql, g_ql);
    cudaGetSymbolAddress((void**)&kh, g_kh);     cudaGetSymbolAddress((void**)&kl, g_kl);
    cudaGetSymbolAddress((void**)&v, g_v);
    cudaGetSymbolAddress((void**)&vth, g_vth);   cudaGetSymbolAddress((void**)&vtl, g_vtl);
    cudaGetSymbolAddress((void**)&s, g_s);
    cudaGetSymbolAddress((void**)&ph, g_ph);     cudaGetSymbolAddress((void**)&pl, g_pl);

    const float scale = 1.0f / sqrtf((float)DKK);

    // 0. per-batch lengths
    compute_len<<<BB, 256>>>(mask);

    // 1. split x into bf16 hi/lo
    {
        long long n4 = (long long)MTOT * DD / 4;
        split_fp32<<<(unsigned)((n4 + 255) / 256), 256>>>(x, xh, xl, n4);
    }
    // 2. transpose + split weights:  W[K,N] -> WT[N,K]
    transpose_split<<<dim3(DKK / 32, DD / 32, 1), 256>>>(Wq, wqth, wqtl, DD, DKK, 0, 0);
    transpose_split<<<dim3(DKK / 32, DD / 32, 1), 256>>>(Wk, wkth, wktl, DD, DKK, 0, 0);
    transpose_split<<<dim3(DD / 32, DD / 32, 1), 256>>>(Wv, wvth, wvtl, DD, DD, 0, 0);

    // 3. projections: q, k (skip rows >= len, write bf16 hi/lo); v full fp32
    gemm_bf16x3<false, false, true, true, 1><<<dim3(1, MTOT / 128, 1), 256, SMEM_BYTES>>>(
        xh, xl, wqth, wqtl, bq, nullptr, qh, ql, MTOT, DKK, DD, 0, 0, 0, 1.0f);
    gemm_bf16x3<false, false, true, true, 1><<<dim3(1, MTOT / 128, 1), 256, SMEM_BYTES>>>(
        xh, xl, wkth, wktl, bk, nullptr, kh, kl, MTOT, DKK, DD, 0, 0, 0, 1.0f);
    gemm_bf16x3<false, false, true, false, 0><<<dim3(DD / 128, MTOT / 128, 1), 256, SMEM_BYTES>>>(
        xh, xl, wvth, wvtl, bv, v, nullptr, nullptr, MTOT, DD, DD, 0, 0, 0, 1.0f);

    // 4. transpose+split v per batch; V column means
    transpose_split<<<dim3(DD / 32, SS / 32, BB), 256>>>(
        v, vth, vtl, SS, DD, (long long)SS * DD, (long long)SS * DD);
    v_colmean<<<dim3(DD / 256, BB), 256>>>();

    // 5. scores: lower-triangle tiles, both dims clipped to len
    gemm_bf16x3<true, false, false, false, 2><<<dim3(SS / 128, SS / 128, BB), 256, SMEM_BYTES>>>(
        qh, ql, kh, kl, nullptr, s, nullptr, nullptr, SS, SS, DKK,
        (long long)SS * DKK, (long long)SS * DKK, (long long)SS * SS, scale);

    // 6. masked softmax -> P (bf16 hi/lo)
    masked_softmax<<<dim3(SS, BB), 256>>>(mask);

    // 7. out = P @ V^T-layout, K truncated to min(causal, len); skip rows>=len
    gemm_bf16x3<false, true, false, false, 3><<<dim3(DD / 128, SS / 128, BB), 256, SMEM_BYTES>>>(
        ph, pl, vth, vtl, nullptr, out, nullptr, nullptr, SS, DD, SS,
        (long long)SS * SS, (long long)DD * SS, (long long)SS * DD, 1.0f);

    // 8. padded rows <- uniform attention (V column mean)
    scatter_padded<<<dim3(SS, BB), 256>>>(mask, out);
}